// round 7
// baseline (speedup 1.0000x reference)
#include <cuda_runtime.h>
#include <cuda_bf16.h>
#include <cstdint>
#include <math.h>

// dims: N=64, C=64, T=512, V=25, S=3, I=16
// ---------------- device scratch (no cudaMalloc allowed) ----------------
__device__ float g_Apart[1536u * 1024u];      // [(n*3+s)*8+seg][v32*32]
__device__ float g_Aeff[192 * 625];           // [n*3+s][v][w]
__device__ __nv_bfloat16 g_Wdh[64 * 200];     // [o][k=s*64+c pad200] bf16 hi
__device__ __nv_bfloat16 g_Wdl[64 * 200];     // bf16 lo
__device__ __nv_bfloat16 g_Wt9h[9 * 64 * 72]; // [k][c][o pad72] bf16 hi
__device__ __nv_bfloat16 g_Wt9l[9 * 64 * 72]; // bf16 lo
__device__ float g_y[52428800u];              // pre-BN y; later reused for TCN z
__device__ float g_y2[52428800u];              // post BN1+residual+relu
__device__ float g_bnS[64u * 8192u];
__device__ float g_bnQ[64u * 8192u];
__device__ float g_stats[256];                // [off+c]=mean, [off+64+c]=rstd
__device__ float g_meanT[64 * 64 * 25];
__device__ float g_gs[64 * 25];               // 1+sigmoid spatial gate
__device__ float g_meanV[64 * 64 * 512];
__device__ float g_gt[64 * 512];              // 1+sigmoid temporal gate
__device__ float g_gc[64 * 64];               // 1+sigmoid channel gate

// ---------------- mma helpers ----------------
__device__ __forceinline__ unsigned su32(const void* p) {
    return (unsigned)__cvta_generic_to_shared(p);
}
__device__ __forceinline__ void ldsm4(unsigned addr, unsigned* r) {
    asm volatile("ldmatrix.sync.aligned.m8n8.x4.shared.b16 {%0,%1,%2,%3}, [%4];"
                 : "=r"(r[0]), "=r"(r[1]), "=r"(r[2]), "=r"(r[3]) : "r"(addr));
}
__device__ __forceinline__ void ldsm4t(unsigned addr, unsigned* r) {
    asm volatile("ldmatrix.sync.aligned.m8n8.x4.trans.shared.b16 {%0,%1,%2,%3}, [%4];"
                 : "=r"(r[0]), "=r"(r[1]), "=r"(r[2]), "=r"(r[3]) : "r"(addr));
}
__device__ __forceinline__ void mma16816(float* d, const unsigned* a, const unsigned* b) {
    asm volatile("mma.sync.aligned.m16n8k16.row.col.f32.bf16.bf16.f32 "
                 "{%0,%1,%2,%3}, {%4,%5,%6,%7}, {%8,%9}, {%0,%1,%2,%3};"
                 : "+f"(d[0]), "+f"(d[1]), "+f"(d[2]), "+f"(d[3])
                 : "r"(a[0]), "r"(a[1]), "r"(a[2]), "r"(a[3]), "r"(b[0]), "r"(b[1]));
}

// ---------------- weight prep ----------------
__global__ void k_prep(const float* __restrict__ Wd, const float* __restrict__ tw) {
    int tid = blockIdx.x * 256 + threadIdx.x;
    int stride = gridDim.x * 256;
    // GCN stage2 weights, A-side layout [o][k pad 200], k = s*64+c
    for (int i = tid; i < 64 * 200; i += stride) {
        int o = i / 200, k = i % 200;
        float w = 0.f;
        if (k < 192) { int s = k / 64, c = k % 64; w = Wd[s * 4096 + o * 64 + c]; }
        __nv_bfloat16 h = __float2bfloat16(w);
        g_Wdh[i] = h;
        g_Wdl[i] = __float2bfloat16(w - __bfloat162float(h));
    }
    // bf16 split TCN weights: [k][c][o pad 72]
    for (int i = tid; i < 9 * 64 * 72; i += stride) {
        int k = i / 4608, r = i % 4608, c = r / 72, o = r % 72;
        float w = (o < 64) ? tw[o * 576 + c * 9 + k] : 0.f;
        __nv_bfloat16 h = __float2bfloat16(w);
        g_Wt9h[i] = h;
        g_Wt9l[i] = __float2bfloat16(w - __bfloat162float(h));
    }
}

// ---------------- fused fa/fb projection + Gram partials ----------------
__global__ void __launch_bounds__(256) k_fabgram(
    const float* __restrict__ x, const float* __restrict__ Wa, const float* __restrict__ ba,
    const float* __restrict__ Wb, const float* __restrict__ bb)
{
    extern __shared__ float sm[];
    float* xs  = sm;                 // [c=64][4t*32v] = 8192
    float* Wab = sm + 8192;          // [s*32+r][stride65] = 6240
    float* fs  = sm + 8192 + 6240;   // [(s*2+side)][64k][32v] = 12288
    int n = blockIdx.x, seg = blockIdx.y, tid = threadIdx.x;
    int tseg0 = seg * 64;

    for (int idx = tid; idx < 3 * 32 * 64; idx += 256) {
        int s = idx / 2048, r = (idx / 64) % 32, c = idx % 64;
        float w = (r < 16) ? Wa[s * 1024 + r * 64 + c] : Wb[s * 1024 + (r - 16) * 64 + c];
        Wab[(s * 32 + r) * 65 + c] = w;
    }
    int ig = tid & 7;
    int vq = (tid >> 3) & 7;
    int tloc = tid >> 6;

    float bias[3][4];
#pragma unroll
    for (int s = 0; s < 3; s++)
#pragma unroll
        for (int j = 0; j < 4; j++) {
            int r = ig * 4 + j;
            bias[s][j] = (r < 16) ? ba[s * 16 + r] : bb[s * 16 + (r - 16)];
        }
    int side = ig >> 2;
    int gv = tid >> 3, gw4 = (tid & 7) * 4;

    float gacc[3][4];
#pragma unroll
    for (int s = 0; s < 3; s++)
#pragma unroll
        for (int q = 0; q < 4; q++) gacc[s][q] = 0.f;

    for (int sub = 0; sub < 16; sub++) {
        int t0 = tseg0 + sub * 4;
        for (int idx = tid; idx < 8192; idx += 256) {
            int c = idx >> 7, r = idx & 127, t = r >> 5, v = r & 31;
            xs[idx] = (v < 25) ? x[(((size_t)n * 64 + c) * 512 + t0 + t) * 25 + v] : 0.f;
        }
        __syncthreads();
        float4 facc[3][4];
#pragma unroll
        for (int s = 0; s < 3; s++)
#pragma unroll
            for (int j = 0; j < 4; j++) {
                float b0 = bias[s][j];
                facc[s][j] = make_float4(b0, b0, b0, b0);
            }
        for (int c = 0; c < 64; c++) {
            float4 X = *(const float4*)&xs[c * 128 + tloc * 32 + vq * 4];
#pragma unroll
            for (int s = 0; s < 3; s++)
#pragma unroll
                for (int j = 0; j < 4; j++) {
                    float w = Wab[(s * 32 + ig * 4 + j) * 65 + c];
                    facc[s][j].x += w * X.x; facc[s][j].y += w * X.y;
                    facc[s][j].z += w * X.z; facc[s][j].w += w * X.w;
                }
        }
#pragma unroll
        for (int s = 0; s < 3; s++)
#pragma unroll
            for (int j = 0; j < 4; j++) {
                int kl = tloc * 16 + (ig & 3) * 4 + j;
                *(float4*)&fs[(s * 2 + side) * 2048 + kl * 32 + vq * 4] = facc[s][j];
            }
        __syncthreads();
#pragma unroll
        for (int s = 0; s < 3; s++) {
            const float* fap = &fs[(s * 2 + 0) * 2048];
            const float* fbp = &fs[(s * 2 + 1) * 2048];
            for (int kk = 0; kk < 64; kk++) {
                float fav = fap[kk * 32 + gv];
                float4 f4 = *(const float4*)&fbp[kk * 32 + gw4];
                gacc[s][0] += fav * f4.x; gacc[s][1] += fav * f4.y;
                gacc[s][2] += fav * f4.z; gacc[s][3] += fav * f4.w;
            }
        }
        __syncthreads();
    }
#pragma unroll
    for (int s = 0; s < 3; s++) {
        float* p = &g_Apart[((size_t)((n * 3 + s) * 8 + seg)) * 1024 + gv * 32 + gw4];
        p[0] = gacc[s][0]; p[1] = gacc[s][1]; p[2] = gacc[s][2]; p[3] = gacc[s][3];
    }
}

__global__ void k_gram2(const float* __restrict__ PA, const float* __restrict__ alpha) {
    int ns = blockIdx.x; int s = ns % 3;
    float al = alpha[0];
    for (int p = threadIdx.x; p < 625; p += 256) {
        int v = p / 25, w = p % 25;
        float sum = 0;
        for (int seg = 0; seg < 8; seg++)
            sum += g_Apart[((size_t)ns * 8 + seg) * 1024 + v * 32 + w];
        float A1 = tanhf(sum * (1.0f / 8192.0f));
        g_Aeff[ns * 625 + p] = PA[s * 625 + p] + al * A1;
    }
}

// ---------------- GCN via mma.sync bf16-split + BN1 partial epilogue ----------------
// Per block (tcb of 4 t, n): stage1 scalar z = x·Ae -> bf16 split smem [k=192][slot pad120],
// stage2 MMA: D[o64][slot112] = Wd[o][k192] * z[k][slot]. Valid slots 100 = 4t*25v.
#define GCN_SMEM 207888
__global__ void __launch_bounds__(512) k_gcnmma(const float* __restrict__ x) {
    extern __shared__ char sraw[];
    float* xT = (float*)sraw;                             // [100 slot'][68 c]  27200B
    float* ae = (float*)(sraw + 27200);                   // [3][25][28]        8400B
    __nv_bfloat16* Zh = (__nv_bfloat16*)(sraw + 35600);   // [192][120]         46080B
    __nv_bfloat16* Zl = (__nv_bfloat16*)(sraw + 81680);   //                    46080B
    __nv_bfloat16* Wh = (__nv_bfloat16*)(sraw + 127760);  // [64][200]          25600B
    __nv_bfloat16* Wl = (__nv_bfloat16*)(sraw + 153360);  //                    25600B
    float* zout = (float*)(sraw + 178960);                // [64][113]          28928B
    int tcb = blockIdx.x, n = blockIdx.y;
    int t0 = tcb * 4, tid = threadIdx.x;
    int wid = tid >> 5, lane = tid & 31;

    // stage x transposed [slot'=t*25+v][c]
    for (int idx = tid; idx < 6400; idx += 512) {
        int c = idx / 100, r = idx % 100;
        xT[r * 68 + c] = x[(((size_t)n * 64 + c) * 512 + t0 + r / 25) * 25 + r % 25];
    }
    // stage Ae padded [s][v][w28]
    for (int idx = tid; idx < 2100; idx += 512) {
        int s = idx / 700, r = idx % 700, v = r / 28, w = r % 28;
        ae[idx] = (w < 25) ? g_Aeff[(size_t)(n * 3 + s) * 625 + v * 25 + w] : 0.f;
    }
    // stage W (bf16 hi/lo), flat 32-bit copy
    {
        unsigned* dh = (unsigned*)Wh; const unsigned* sh = (const unsigned*)g_Wdh;
        unsigned* dl = (unsigned*)Wl; const unsigned* sl = (const unsigned*)g_Wdl;
        for (int idx = tid; idx < 6400; idx += 512) { dh[idx] = sh[idx]; dl[idx] = sl[idx]; }
    }
    // zero-fill pad slot cols [100,120) of Zh/Zl
    for (int idx = tid; idx < 1920; idx += 512) {
        int k = idx / 10, p = idx % 10;
        *(unsigned*)&Zh[k * 120 + 100 + p * 2] = 0;
        *(unsigned*)&Zl[k * 120 + 100 + p * 2] = 0;
    }
    __syncthreads();

    // stage1: thread = (c-quad, w); reuse each x float4 across 3 subsets
    {
        int c0 = (tid & 15) * 4, w = tid >> 4;   // w 0..31, active if <25
        if (w < 25) {
            for (int t = 0; t < 4; t++) {
                float4 a0 = make_float4(0, 0, 0, 0), a1 = a0, a2 = a0;
                for (int v = 0; v < 25; v++) {
                    float4 X = *(const float4*)&xT[(t * 25 + v) * 68 + c0];
                    float e0 = ae[v * 28 + w];
                    float e1 = ae[700 + v * 28 + w];
                    float e2 = ae[1400 + v * 28 + w];
                    a0.x += X.x * e0; a0.y += X.y * e0; a0.z += X.z * e0; a0.w += X.w * e0;
                    a1.x += X.x * e1; a1.y += X.y * e1; a1.z += X.z * e1; a1.w += X.w * e1;
                    a2.x += X.x * e2; a2.y += X.y * e2; a2.z += X.z * e2; a2.w += X.w * e2;
                }
                int slot = t * 25 + w;
                float zv[3][4] = {{a0.x, a0.y, a0.z, a0.w},
                                  {a1.x, a1.y, a1.z, a1.w},
                                  {a2.x, a2.y, a2.z, a2.w}};
#pragma unroll
                for (int s = 0; s < 3; s++)
#pragma unroll
                    for (int i = 0; i < 4; i++) {
                        float val = zv[s][i];
                        __nv_bfloat16 h = __float2bfloat16(val);
                        int k = s * 64 + c0 + i;
                        Zh[k * 120 + slot] = h;
                        Zl[k * 120 + slot] = __float2bfloat16(val - __bfloat162float(h));
                    }
            }
        }
    }
    __syncthreads();

    // stage2 MMA: 28 tiles (4 m16 o-tiles x 7 n16 slot-groups) over 16 warps
    int mt[2], nb[2], cnt = 0;
    for (int tl = wid; tl < 28; tl += 16) { mt[cnt] = tl & 3; nb[cnt] = (tl >> 2) * 16; cnt++; }
    float acc[2][8];
#pragma unroll
    for (int q = 0; q < 2; q++)
#pragma unroll
        for (int i = 0; i < 8; i++) acc[q][i] = 0.f;

    unsigned baseW = su32(Wh), baseZ = su32(Zh);
    int arow = lane & 15, acol8 = (lane >> 4) << 3;
#pragma unroll
    for (int ks = 0; ks < 12; ks++) {
        int k0 = ks * 16;
#pragma unroll
        for (int q = 0; q < 2; q++) {
            if (q >= cnt) break;
            unsigned wh_[4], wl_[4], zh_[4], zl_[4];
            unsigned aaddr = baseW + (unsigned)(((mt[q] * 16 + arow) * 200 + k0 + acol8) * 2);
            ldsm4(aaddr, wh_);
            ldsm4(aaddr + 25600u, wl_);
            unsigned baddr = baseZ + (unsigned)(((k0 + arow) * 120 + nb[q] + acol8) * 2);
            ldsm4t(baddr, zh_);
            ldsm4t(baddr + 46080u, zl_);
            mma16816(&acc[q][0], wh_, &zh_[0]);
            mma16816(&acc[q][0], wh_, &zl_[0]);
            mma16816(&acc[q][0], wl_, &zh_[0]);
            mma16816(&acc[q][4], wh_, &zh_[2]);
            mma16816(&acc[q][4], wh_, &zl_[2]);
            mma16816(&acc[q][4], wl_, &zh_[2]);
        }
    }
    // fragment store: D rows = o, cols = slot
#pragma unroll
    for (int q = 0; q < 2; q++) {
        if (q >= cnt) break;
        int orow = mt[q] * 16 + (lane >> 2);
#pragma unroll
        for (int h = 0; h < 2; h++) {
            int cb = nb[q] + h * 8 + ((lane & 3) << 1);
            zout[orow * 113 + cb] = acc[q][h * 4 + 0];
            zout[orow * 113 + cb + 1] = acc[q][h * 4 + 1];
            zout[(orow + 8) * 113 + cb] = acc[q][h * 4 + 2];
            zout[(orow + 8) * 113 + cb + 1] = acc[q][h * 4 + 3];
        }
    }
    __syncthreads();
    // coalesced global store of valid slots
    for (int idx = tid; idx < 6400; idx += 512) {
        int o = idx / 100, sl = idx % 100;
        g_y[((size_t)(n * 64 + o) * 512 + t0) * 25 + sl] = zout[o * 113 + sl];
    }
    // BN1 partials from zout (valid slots only), reuse ae region
    float* red = ae;
    {
        int o = tid >> 3, sub = tid & 7;
        float a = 0, b = 0;
        for (int sl = sub; sl < 100; sl += 8) {
            float vv = zout[o * 113 + sl];
            a += vv; b += vv * vv;
        }
        red[tid] = a; red[512 + tid] = b;
    }
    __syncthreads();
    if (tid < 64) {
        float a = 0, b = 0;
        for (int p = 0; p < 8; p++) { a += red[tid * 8 + p]; b += red[512 + tid * 8 + p]; }
        g_bnS[(size_t)tid * 8192 + n * 128 + tcb] = a;
        g_bnQ[(size_t)tid * 8192 + n * 128 + tcb] = b;
    }
}

__global__ void k_bnfin(int cnt, int off) {
    __shared__ float s1[256], s2[256];
    int c = blockIdx.x, tid = threadIdx.x;
    float a = 0, b = 0;
    for (int i = tid; i < cnt; i += 256) {
        a += g_bnS[(size_t)c * 8192 + i];
        b += g_bnQ[(size_t)c * 8192 + i];
    }
    s1[tid] = a; s2[tid] = b; __syncthreads();
    for (int st = 128; st > 0; st >>= 1) {
        if (tid < st) { s1[tid] += s1[tid + st]; s2[tid] += s2[tid + st]; }
        __syncthreads();
    }
    if (tid == 0) {
        float m = s1[0] / 819200.0f;
        float v = s2[0] / 819200.0f - m * m;
        g_stats[off + c] = m;
        g_stats[off + 64 + c] = rsqrtf(v + 1e-5f);
    }
}

// BN1 apply + residual + relu -> g_y2, fused T-mean partials -> g_meanT
__global__ void __launch_bounds__(256) k_bnapply_mt(
    const float* __restrict__ gm, const float* __restrict__ bt, const float* __restrict__ x)
{
    __shared__ float red[8 * 33];
    int nc = blockIdx.x, tid = threadIdx.x, lane = tid & 31, tg = tid >> 5;
    int c = nc & 63;
    float m = g_stats[c], r = g_stats[64 + c];
    float sc = r * gm[c], sb = bt[c] - m * sc;
    float a = 0;
    if (lane < 25) {
        size_t base = (size_t)nc * 12800 + lane;
        for (int t = tg; t < 512; t += 8) {
            float y = g_y[base + t * 25];
            float o = fmaxf(y * sc + sb + x[base + t * 25], 0.f);
            g_y2[base + t * 25] = o;
            a += o;
        }
        red[tg * 33 + lane] = a;
    }
    __syncthreads();
    if (tid < 25) {
        float s = 0;
        for (int g = 0; g < 8; g++) s += red[g * 33 + tid];
        g_meanT[nc * 25 + tid] = s * (1.f / 512.f);
    }
}

// ---------------- attention chain ----------------
__global__ void k_sattn(const float* __restrict__ saw, const float* __restrict__ sab) {
    int n = blockIdx.x, v = threadIdx.x;
    if (v < 25) {
        float acc = sab[0];
        for (int c = 0; c < 64; c++) {
            const float* m = &g_meanT[(n * 64 + c) * 25];
            const float* w = &saw[c * 25];
#pragma unroll
            for (int j = 0; j < 25; j++) {
                int vv = v + j - 12;
                if (vv >= 0 && vv < 25) acc += w[j] * m[vv];
            }
        }
        g_gs[n * 25 + v] = 1.f + 1.f / (1.f + expf(-acc));
    }
}

__global__ void __launch_bounds__(256) k_meanV() {
    __shared__ float sgs[25];
    int nc = blockIdx.x, tid = threadIdx.x;
    int n = nc >> 6;
    if (tid < 25) sgs[tid] = g_gs[n * 25 + tid];
    __syncthreads();
    for (int t = tid; t < 512; t += 256) {
        const float* row = &g_y2[(size_t)nc * 12800 + t * 25];
        float a = 0;
#pragma unroll
        for (int v = 0; v < 25; v++) a += row[v] * sgs[v];
        g_meanV[nc * 512 + t] = a * (1.f / 25.f);
    }
}

__global__ void k_tattn(const float* __restrict__ taw, const float* __restrict__ tab) {
    int n = blockIdx.x, tid = threadIdx.x;
    for (int t = tid; t < 512; t += 256) {
        float acc = tab[0];
        for (int c = 0; c < 64; c++) {
            const float* m = &g_meanV[(n * 64 + c) * 512];
            const float* w = &taw[c * 9];
#pragma unroll
            for (int j = 0; j < 9; j++) {
                int tt = t + j - 4;
                if (tt >= 0 && tt < 512) acc += w[j] * m[tt];
            }
        }
        g_gt[n * 512 + t] = 1.f + 1.f / (1.f + expf(-acc));
    }
}

__global__ void k_cse(const float* __restrict__ f1w, const float* __restrict__ f1b,
                      const float* __restrict__ f2w, const float* __restrict__ f2b) {
    __shared__ float sm3[64], sh[32];
    int n = blockIdx.x, c = threadIdx.x;
    const float* m = &g_meanV[(n * 64 + c) * 512];
    const float* gt = &g_gt[n * 512];
    float a = 0;
    for (int t = 0; t < 512; t++) a += m[t] * gt[t];
    sm3[c] = a * (1.f / 512.f);
    __syncthreads();
    if (c < 32) {
        float h = f1b[c];
        for (int k = 0; k < 64; k++) h += f1w[c * 64 + k] * sm3[k];
        sh[c] = fmaxf(h, 0.f);
    }
    __syncthreads();
    float o = f2b[c];
    for (int j = 0; j < 32; j++) o += f2w[c * 32 + j] * sh[j];
    g_gc[n * 64 + c] = 1.f + 1.f / (1.f + expf(-o));
}

// ---------------- TCN via mma.sync bf16-split + BN2 partial epilogue ----------------
#define TCN_SMEM 189440
__global__ void __launch_bounds__(512) k_tcn() {
    extern __shared__ char smemraw[];
    __nv_bfloat16* Ah = (__nv_bfloat16*)smemraw;                 // [408][72]
    __nv_bfloat16* Wh = (__nv_bfloat16*)(smemraw + 117504);      // [64][72]
    __nv_bfloat16* Wl = (__nv_bfloat16*)(smemraw + 126720);
    float* zout = (float*)(smemraw + 135936);                    // [64][209]
    __shared__ float gsg[25], gtg[17], gcg[64];
    int tcb = blockIdx.x, n = blockIdx.y;
    int t0 = tcb * 8, tid = threadIdx.x;
    int wid = tid >> 5, lane = tid & 31;

    if (tid < 25) gsg[tid] = g_gs[n * 25 + tid];
    if (tid >= 32 && tid < 49) {
        int tin = t0 - 4 + (tid - 32);
        gtg[tid - 32] = (tin >= 0 && tin < 512) ? g_gt[n * 512 + tin] : 0.f;
    }
    if (tid >= 64 && tid < 128) gcg[tid - 64] = g_gc[n * 64 + (tid - 64)];
    __syncthreads();

    for (int idx = tid; idx < 408 * 64; idx += 512) {
        int c = idx / 408, s = idx - c * 408;
        int tvg = (t0 - 4) * 25 + s;
        float val = 0.f;
        if (tvg >= 0 && tvg < 12800)
            val = g_y2[(size_t)(n * 64 + c) * 12800 + tvg] * gsg[s % 25] * gtg[s / 25] * gcg[c];
        __nv_bfloat16 h = __float2bfloat16(val);
        Ah[s * 72 + c] = h;
        Ah[29376 + s * 72 + c] = __float2bfloat16(val - __bfloat162float(h));
    }

    int mt[4], nb[4], cnt = 0;
    for (int tl = wid; tl < 52; tl += 16) { mt[cnt] = tl % 13; nb[cnt] = (tl / 13) * 16; cnt++; }
    float acc[4][8];
#pragma unroll
    for (int q = 0; q < 4; q++)
#pragma unroll
        for (int i = 0; i < 8; i++) acc[q][i] = 0.f;

    unsigned baseA = su32(Ah), baseW = su32(Wh);
    int arow = lane & 15, acol8 = (lane >> 4) << 3;

    for (int tap = 0; tap < 9; tap++) {
        __syncthreads();
        for (int idx = tid; idx < 4608; idx += 512) {
            Wh[idx] = g_Wt9h[tap * 4608 + idx];
            Wl[idx] = g_Wt9l[tap * 4608 + idx];
        }
        __syncthreads();
#pragma unroll
        for (int q = 0; q < 4; q++) {
            if (q >= cnt) break;
            int rb = mt[q] * 16 + 25 * tap;
#pragma unroll
            for (int ks = 0; ks < 4; ks++) {
                int c0 = ks * 16;
                unsigned aaddr = baseA + (unsigned)(((rb + arow) * 72 + c0 + acol8) * 2);
                unsigned ah[4], al[4], bh[4], bl[4];
                ldsm4(aaddr, ah);
                ldsm4(aaddr + 58752u, al);
                unsigned baddr = baseW + (unsigned)(((c0 + arow) * 72 + nb[q] + acol8) * 2);
                ldsm4t(baddr, bh);
                ldsm4t(baddr + 9216u, bl);
                mma16816(&acc[q][0], ah, &bh[0]);
                mma16816(&acc[q][0], ah, &bl[0]);
                mma16816(&acc[q][0], al, &bh[0]);
                mma16816(&acc[q][4], ah, &bh[2]);
                mma16816(&acc[q][4], ah, &bl[2]);
                mma16816(&acc[q][4], al, &bh[2]);
            }
        }
    }
    __syncthreads();
#pragma unroll
    for (int q = 0; q < 4; q++) {
        if (q >= cnt) break;
#pragma unroll
        for (int h = 0; h < 2; h++) {
            int o0 = nb[q] + h * 8 + ((lane & 3) << 1);
            int r0 = mt[q] * 16 + (lane >> 2);
            zout[o0 * 209 + r0] = acc[q][h * 4 + 0];
            zout[(o0 + 1) * 209 + r0] = acc[q][h * 4 + 1];
            zout[o0 * 209 + r0 + 8] = acc[q][h * 4 + 2];
            zout[(o0 + 1) * 209 + r0 + 8] = acc[q][h * 4 + 3];
        }
    }
    __syncthreads();
    for (int idx = tid; idx < 64 * 200; idx += 512) {
        int o = idx / 200, sl = idx - o * 200;
        g_y[((size_t)(n * 64 + o) * 512 + t0) * 25 + sl] = zout[o * 209 + sl];
    }
    float* red = (float*)Wh;
    {
        int o = tid >> 3, sub = tid & 7;
        float a = 0, b = 0;
        for (int sl = sub; sl < 200; sl += 8) {
            float v = zout[o * 209 + sl];
            a += v; b += v * v;
        }
        red[tid] = a; red[512 + tid] = b;
    }
    __syncthreads();
    if (tid < 64) {
        float a = 0, b = 0;
        for (int p = 0; p < 8; p++) { a += red[tid * 8 + p]; b += red[512 + tid * 8 + p]; }
        g_bnS[(size_t)tid * 8192 + n * 64 + tcb] = a;
        g_bnQ[(size_t)tid * 8192 + n * 64 + tcb] = b;
    }
}

// final: out = relu(bn2(g_y) + x), vectorized
__global__ void __launch_bounds__(256) k_bnapply2(
    const float* __restrict__ gm, const float* __restrict__ bt,
    const float* __restrict__ x, float* __restrict__ out)
{
    size_t i4 = (size_t)blockIdx.x * 256 + threadIdx.x;
    size_t flat = i4 * 4;
    int c = (int)((flat / 12800) % 64);
    float m = g_stats[128 + c], r = g_stats[192 + c];
    float sc = r * gm[c];
    float sb = bt[c] - m * sc;
    float4 Y = *(const float4*)&g_y[flat];
    float4 X = *(const float4*)&x[flat];
    float4 O;
    O.x = fmaxf(Y.x * sc + sb + X.x, 0.f);
    O.y = fmaxf(Y.y * sc + sb + X.y, 0.f);
    O.z = fmaxf(Y.z * sc + sb + X.z, 0.f);
    O.w = fmaxf(Y.w * sc + sb + X.w, 0.f);
    *(float4*)&out[flat] = O;
}

// ---------------- launcher ----------------
extern "C" void kernel_launch(void* const* d_in, const int* in_sizes, int n_in,
                              void* d_out, int out_size) {
    const float* x   = (const float*)d_in[0];
    const float* PA  = (const float*)d_in[1];
    const float* alp = (const float*)d_in[2];
    const float* Wa  = (const float*)d_in[3];
    const float* ba  = (const float*)d_in[4];
    const float* Wb  = (const float*)d_in[5];
    const float* bb  = (const float*)d_in[6];
    const float* Wd  = (const float*)d_in[7];
    const float* bng = (const float*)d_in[9];
    const float* bnb = (const float*)d_in[10];
    const float* saw = (const float*)d_in[11];
    const float* sab = (const float*)d_in[12];
    const float* taw = (const float*)d_in[13];
    const float* tab = (const float*)d_in[14];
    const float* f1w = (const float*)d_in[15];
    const float* f1b = (const float*)d_in[16];
    const float* f2w = (const float*)d_in[17];
    const float* f2b = (const float*)d_in[18];
    const float* tw  = (const float*)d_in[19];
    const float* tbg = (const float*)d_in[21];
    const float* tbb = (const float*)d_in[22];
    float* out = (float*)d_out;

    cudaFuncSetAttribute(k_fabgram, cudaFuncAttributeMaxDynamicSharedMemorySize, 106880);
    cudaFuncSetAttribute(k_gcnmma, cudaFuncAttributeMaxDynamicSharedMemorySize, GCN_SMEM);
    cudaFuncSetAttribute(k_tcn, cudaFuncAttributeMaxDynamicSharedMemorySize, TCN_SMEM);

    k_prep<<<64, 256>>>(Wd, tw);
    k_fabgram<<<dim3(64, 8), 256, 106880>>>(x, Wa, ba, Wb, bb);
    k_gram2<<<192, 256>>>(PA, alp);
    k_gcnmma<<<dim3(128, 64), 512, GCN_SMEM>>>(x);
    k_bnfin<<<64, 256>>>(8192, 0);
    k_bnapply_mt<<<4096, 256>>>(bng, bnb, x);
    k_sattn<<<64, 32>>>(saw, sab);
    k_meanV<<<4096, 256>>>();
    k_tattn<<<64, 256>>>(taw, tab);
    k_cse<<<64, 64>>>(f1w, f1b, f2w, f2b);
    k_tcn<<<dim3(64, 64), 512, TCN_SMEM>>>();
    k_bnfin<<<64, 256>>>(4096, 128);
    k_bnapply2<<<51200, 256>>>(tbg, tbb, x, out);
}

// round 8
// speedup vs baseline: 1.0716x; 1.0716x over previous
#include <cuda_runtime.h>
#include <cuda_bf16.h>
#include <cstdint>
#include <math.h>

// dims: N=64, C=64, T=512, V=25, S=3, I=16
// ---------------- device scratch (no cudaMalloc allowed) ----------------
__device__ float g_Apart[1536u * 1024u];      // [(n*3+s)*8+seg][v32*32]
__device__ float g_Aeff[192 * 625];           // [n*3+s][v][w]
__device__ float g_Wdt[3 * 64 * 64];          // [s][c][o]
__device__ __nv_bfloat16 g_Wt9h[9 * 64 * 72]; // [k][c][o pad72] bf16 hi
__device__ __nv_bfloat16 g_Wt9l[9 * 64 * 72]; // bf16 lo
__device__ float g_y[52428800u];              // pre-BN y; later reused for TCN z
__device__ float g_y2[52428800u];             // post BN1+residual+relu
__device__ float g_bnS[64u * 8192u];
__device__ float g_bnQ[64u * 8192u];
__device__ float g_stats[256];                // [off+c]=mean, [off+64+c]=rstd
__device__ float g_meanT[64 * 64 * 25];
__device__ float g_gs[64 * 25];               // 1+sigmoid spatial gate
__device__ float g_meanV[64 * 64 * 512];
__device__ float g_gt[64 * 512];              // 1+sigmoid temporal gate
__device__ float g_gc[64 * 64];               // 1+sigmoid channel gate

// ---------------- mma helpers ----------------
__device__ __forceinline__ unsigned su32(const void* p) {
    return (unsigned)__cvta_generic_to_shared(p);
}
__device__ __forceinline__ void ldsm4(unsigned addr, unsigned* r) {
    asm volatile("ldmatrix.sync.aligned.m8n8.x4.shared.b16 {%0,%1,%2,%3}, [%4];"
                 : "=r"(r[0]), "=r"(r[1]), "=r"(r[2]), "=r"(r[3]) : "r"(addr));
}
__device__ __forceinline__ void ldsm4t(unsigned addr, unsigned* r) {
    asm volatile("ldmatrix.sync.aligned.m8n8.x4.trans.shared.b16 {%0,%1,%2,%3}, [%4];"
                 : "=r"(r[0]), "=r"(r[1]), "=r"(r[2]), "=r"(r[3]) : "r"(addr));
}
__device__ __forceinline__ void mma16816(float* d, const unsigned* a, const unsigned* b) {
    asm volatile("mma.sync.aligned.m16n8k16.row.col.f32.bf16.bf16.f32 "
                 "{%0,%1,%2,%3}, {%4,%5,%6,%7}, {%8,%9}, {%0,%1,%2,%3};"
                 : "+f"(d[0]), "+f"(d[1]), "+f"(d[2]), "+f"(d[3])
                 : "r"(a[0]), "r"(a[1]), "r"(a[2]), "r"(a[3]), "r"(b[0]), "r"(b[1]));
}

// ---------------- weight prep ----------------
__global__ void k_prep(const float* __restrict__ Wd, const float* __restrict__ tw) {
    int tid = blockIdx.x * 256 + threadIdx.x;
    int stride = gridDim.x * 256;
    for (int i = tid; i < 3 * 64 * 64; i += stride) {
        int s = i / 4096, r = i % 4096, c = r / 64, o = r % 64;
        g_Wdt[i] = Wd[s * 4096 + o * 64 + c];
    }
    // bf16 split TCN weights: [k][c][o pad 72]
    for (int i = tid; i < 9 * 64 * 72; i += stride) {
        int k = i / 4608, r = i % 4608, c = r / 72, o = r % 72;
        float w = (o < 64) ? tw[o * 576 + c * 9 + k] : 0.f;
        __nv_bfloat16 h = __float2bfloat16(w);
        g_Wt9h[i] = h;
        g_Wt9l[i] = __float2bfloat16(w - __bfloat162float(h));
    }
}

// ---------------- fused fa/fb projection + Gram partials ----------------
__global__ void __launch_bounds__(256) k_fabgram(
    const float* __restrict__ x, const float* __restrict__ Wa, const float* __restrict__ ba,
    const float* __restrict__ Wb, const float* __restrict__ bb)
{
    extern __shared__ float sm[];
    float* xs  = sm;                 // [c=64][4t*32v] = 8192
    float* Wab = sm + 8192;          // [s*32+r][stride65] = 6240
    float* fs  = sm + 8192 + 6240;   // [(s*2+side)][64k][32v] = 12288
    int n = blockIdx.x, seg = blockIdx.y, tid = threadIdx.x;
    int tseg0 = seg * 64;

    for (int idx = tid; idx < 3 * 32 * 64; idx += 256) {
        int s = idx / 2048, r = (idx / 64) % 32, c = idx % 64;
        float w = (r < 16) ? Wa[s * 1024 + r * 64 + c] : Wb[s * 1024 + (r - 16) * 64 + c];
        Wab[(s * 32 + r) * 65 + c] = w;
    }
    int ig = tid & 7;
    int vq = (tid >> 3) & 7;
    int tloc = tid >> 6;

    float bias[3][4];
#pragma unroll
    for (int s = 0; s < 3; s++)
#pragma unroll
        for (int j = 0; j < 4; j++) {
            int r = ig * 4 + j;
            bias[s][j] = (r < 16) ? ba[s * 16 + r] : bb[s * 16 + (r - 16)];
        }
    int side = ig >> 2;
    int gv = tid >> 3, gw4 = (tid & 7) * 4;

    float gacc[3][4];
#pragma unroll
    for (int s = 0; s < 3; s++)
#pragma unroll
        for (int q = 0; q < 4; q++) gacc[s][q] = 0.f;

    for (int sub = 0; sub < 16; sub++) {
        int t0 = tseg0 + sub * 4;
        for (int idx = tid; idx < 8192; idx += 256) {
            int c = idx >> 7, r = idx & 127, t = r >> 5, v = r & 31;
            xs[idx] = (v < 25) ? x[(((size_t)n * 64 + c) * 512 + t0 + t) * 25 + v] : 0.f;
        }
        __syncthreads();
        float4 facc[3][4];
#pragma unroll
        for (int s = 0; s < 3; s++)
#pragma unroll
            for (int j = 0; j < 4; j++) {
                float b0 = bias[s][j];
                facc[s][j] = make_float4(b0, b0, b0, b0);
            }
        for (int c = 0; c < 64; c++) {
            float4 X = *(const float4*)&xs[c * 128 + tloc * 32 + vq * 4];
#pragma unroll
            for (int s = 0; s < 3; s++)
#pragma unroll
                for (int j = 0; j < 4; j++) {
                    float w = Wab[(s * 32 + ig * 4 + j) * 65 + c];
                    facc[s][j].x += w * X.x; facc[s][j].y += w * X.y;
                    facc[s][j].z += w * X.z; facc[s][j].w += w * X.w;
                }
        }
#pragma unroll
        for (int s = 0; s < 3; s++)
#pragma unroll
            for (int j = 0; j < 4; j++) {
                int kl = tloc * 16 + (ig & 3) * 4 + j;
                *(float4*)&fs[(s * 2 + side) * 2048 + kl * 32 + vq * 4] = facc[s][j];
            }
        __syncthreads();
#pragma unroll
        for (int s = 0; s < 3; s++) {
            const float* fap = &fs[(s * 2 + 0) * 2048];
            const float* fbp = &fs[(s * 2 + 1) * 2048];
            for (int kk = 0; kk < 64; kk++) {
                float fav = fap[kk * 32 + gv];
                float4 f4 = *(const float4*)&fbp[kk * 32 + gw4];
                gacc[s][0] += fav * f4.x; gacc[s][1] += fav * f4.y;
                gacc[s][2] += fav * f4.z; gacc[s][3] += fav * f4.w;
            }
        }
        __syncthreads();
    }
#pragma unroll
    for (int s = 0; s < 3; s++) {
        float* p = &g_Apart[((size_t)((n * 3 + s) * 8 + seg)) * 1024 + gv * 32 + gw4];
        p[0] = gacc[s][0]; p[1] = gacc[s][1]; p[2] = gacc[s][2]; p[3] = gacc[s][3];
    }
}

__global__ void k_gram2(const float* __restrict__ PA, const float* __restrict__ alpha) {
    int ns = blockIdx.x; int s = ns % 3;
    float al = alpha[0];
    for (int p = threadIdx.x; p < 625; p += 256) {
        int v = p / 25, w = p % 25;
        float sum = 0;
        for (int seg = 0; seg < 8; seg++)
            sum += g_Apart[((size_t)ns * 8 + seg) * 1024 + v * 32 + w];
        float A1 = tanhf(sum * (1.0f / 8192.0f));
        g_Aeff[ns * 625 + p] = PA[s * 625 + p] + al * A1;
    }
}

// ---------------- GCN scalar + BN1 partial epilogue (R5 version, known good) ----------------
#define ZST 112
__global__ void __launch_bounds__(256) k_gcn(const float* __restrict__ x) {
    extern __shared__ float sm[];
    float* xT = sm;                      // [t*25+v][stride 68 c]  6800
    float* zs = sm + 6800;               // [c][tw stride 112]     7168
    float* wd = sm + 6800 + 7168;        // [c][o]                 4096
    float* ae = sm + 6800 + 7168 + 4096; // [v][w stride 28]       700
    int tcb = blockIdx.x, n = blockIdx.y;
    int t0 = tcb * 4, tid = threadIdx.x;

    for (int idx = tid; idx < 6400; idx += 256) {
        int c = idx / 100, r = idx % 100, t = r / 25, v = r % 25;
        xT[(t * 25 + v) * 68 + c] = x[(((size_t)n * 64 + c) * 512 + t0 + t) * 25 + v];
    }
    int cg = tid >> 4, tg2 = tid & 15;
    int zt[7], zw[7];
#pragma unroll
    for (int j = 0; j < 7; j++) { int tw = tg2 + 16 * j; zt[j] = tw / 28; zw[j] = tw % 28; }
    int ot = tid & 15, twt = tid >> 4;
    int gt_[7], gw[7];
#pragma unroll
    for (int j = 0; j < 7; j++) { int tw = twt + 16 * j; gt_[j] = tw / 28; gw[j] = tw % 28; }

    float acc[4][7];
#pragma unroll
    for (int i = 0; i < 4; i++)
#pragma unroll
        for (int j = 0; j < 7; j++) acc[i][j] = 0.f;

    for (int s = 0; s < 3; s++) {
        for (int idx = tid; idx < 700; idx += 256) {
            int v = idx / 28, w = idx % 28;
            ae[idx] = (w < 25) ? g_Aeff[(size_t)(n * 3 + s) * 625 + v * 25 + w] : 0.f;
        }
        for (int idx = tid; idx < 4096; idx += 256) wd[idx] = g_Wdt[s * 4096 + idx];
        __syncthreads();
        {
            float tmp[4][7];
#pragma unroll
            for (int i = 0; i < 4; i++)
#pragma unroll
                for (int j = 0; j < 7; j++) tmp[i][j] = 0.f;
            for (int v = 0; v < 25; v++) {
#pragma unroll
                for (int j = 0; j < 7; j++) {
                    float4 X = *(const float4*)&xT[(zt[j] * 25 + v) * 68 + 4 * cg];
                    float a = ae[v * 28 + zw[j]];
                    tmp[0][j] += X.x * a; tmp[1][j] += X.y * a;
                    tmp[2][j] += X.z * a; tmp[3][j] += X.w * a;
                }
            }
#pragma unroll
            for (int i = 0; i < 4; i++)
#pragma unroll
                for (int j = 0; j < 7; j++)
                    zs[(4 * cg + i) * ZST + tg2 + 16 * j] = tmp[i][j];
        }
        __syncthreads();
        for (int c = 0; c < 64; c++) {
            float4 w4 = *(const float4*)&wd[c * 64 + 4 * ot];
#pragma unroll
            for (int j = 0; j < 7; j++) {
                float z = zs[c * ZST + twt + 16 * j];
                acc[0][j] += w4.x * z; acc[1][j] += w4.y * z;
                acc[2][j] += w4.z * z; acc[3][j] += w4.w * z;
            }
        }
        __syncthreads();
    }
#pragma unroll
    for (int j = 0; j < 7; j++) {
        if (gw[j] < 25) {
#pragma unroll
            for (int i = 0; i < 4; i++)
                g_y[(((size_t)n * 64 + 4 * ot + i) * 512 + t0 + gt_[j]) * 25 + gw[j]] = acc[i][j];
        }
    }
    // BN1 partials: padded-w acc slots are exactly 0 (Ae padded to 0) so include all j
#pragma unroll
    for (int i = 0; i < 4; i++) {
        float a = 0, b = 0;
#pragma unroll
        for (int j = 0; j < 7; j++) { a += acc[i][j]; b += acc[i][j] * acc[i][j]; }
        zs[(4 * ot + i) * 16 + twt] = a;
        zs[1792 + (4 * ot + i) * 16 + twt] = b;
    }
    __syncthreads();
    if (tid < 64) {
        float a = 0, b = 0;
        for (int p = 0; p < 16; p++) { a += zs[tid * 16 + p]; b += zs[1792 + tid * 16 + p]; }
        g_bnS[(size_t)tid * 8192 + n * 128 + tcb] = a;
        g_bnQ[(size_t)tid * 8192 + n * 128 + tcb] = b;
    }
}

__global__ void k_bnfin(int cnt, int off) {
    __shared__ float s1[256], s2[256];
    int c = blockIdx.x, tid = threadIdx.x;
    float a = 0, b = 0;
    for (int i = tid; i < cnt; i += 256) {
        a += g_bnS[(size_t)c * 8192 + i];
        b += g_bnQ[(size_t)c * 8192 + i];
    }
    s1[tid] = a; s2[tid] = b; __syncthreads();
    for (int st = 128; st > 0; st >>= 1) {
        if (tid < st) { s1[tid] += s1[tid + st]; s2[tid] += s2[tid + st]; }
        __syncthreads();
    }
    if (tid == 0) {
        float m = s1[0] / 819200.0f;
        float v = s2[0] / 819200.0f - m * m;
        g_stats[off + c] = m;
        g_stats[off + 64 + c] = rsqrtf(v + 1e-5f);
    }
}

// BN1 apply + residual + relu -> g_y2, fused T-mean partials -> g_meanT
__global__ void __launch_bounds__(256) k_bnapply_mt(
    const float* __restrict__ gm, const float* __restrict__ bt, const float* __restrict__ x)
{
    __shared__ float red[8 * 33];
    int nc = blockIdx.x, tid = threadIdx.x, lane = tid & 31, tg = tid >> 5;
    int c = nc & 63;
    float m = g_stats[c], r = g_stats[64 + c];
    float sc = r * gm[c], sb = bt[c] - m * sc;
    float a = 0;
    if (lane < 25) {
        size_t base = (size_t)nc * 12800 + lane;
        for (int t = tg; t < 512; t += 8) {
            float y = g_y[base + t * 25];
            float o = fmaxf(y * sc + sb + x[base + t * 25], 0.f);
            g_y2[base + t * 25] = o;
            a += o;
        }
        red[tg * 33 + lane] = a;
    }
    __syncthreads();
    if (tid < 25) {
        float s = 0;
        for (int g = 0; g < 8; g++) s += red[g * 33 + tid];
        g_meanT[nc * 25 + tid] = s * (1.f / 512.f);
    }
}

// ---------------- attention chain ----------------
__global__ void k_sattn(const float* __restrict__ saw, const float* __restrict__ sab) {
    int n = blockIdx.x, v = threadIdx.x;
    if (v < 25) {
        float acc = sab[0];
        for (int c = 0; c < 64; c++) {
            const float* m = &g_meanT[(n * 64 + c) * 25];
            const float* w = &saw[c * 25];
#pragma unroll
            for (int j = 0; j < 25; j++) {
                int vv = v + j - 12;
                if (vv >= 0 && vv < 25) acc += w[j] * m[vv];
            }
        }
        g_gs[n * 25 + v] = 1.f + 1.f / (1.f + expf(-acc));
    }
}

__global__ void __launch_bounds__(256) k_meanV() {
    __shared__ float sgs[25];
    int nc = blockIdx.x, tid = threadIdx.x;
    int n = nc >> 6;
    if (tid < 25) sgs[tid] = g_gs[n * 25 + tid];
    __syncthreads();
    for (int t = tid; t < 512; t += 256) {
        const float* row = &g_y2[(size_t)nc * 12800 + t * 25];
        float a = 0;
#pragma unroll
        for (int v = 0; v < 25; v++) a += row[v] * sgs[v];
        g_meanV[nc * 512 + t] = a * (1.f / 25.f);
    }
}

__global__ void k_tattn(const float* __restrict__ taw, const float* __restrict__ tab) {
    int n = blockIdx.x, tid = threadIdx.x;
    for (int t = tid; t < 512; t += 256) {
        float acc = tab[0];
        for (int c = 0; c < 64; c++) {
            const float* m = &g_meanV[(n * 64 + c) * 512];
            const float* w = &taw[c * 9];
#pragma unroll
            for (int j = 0; j < 9; j++) {
                int tt = t + j - 4;
                if (tt >= 0 && tt < 512) acc += w[j] * m[tt];
            }
        }
        g_gt[n * 512 + t] = 1.f + 1.f / (1.f + expf(-acc));
    }
}

__global__ void k_cse(const float* __restrict__ f1w, const float* __restrict__ f1b,
                      const float* __restrict__ f2w, const float* __restrict__ f2b) {
    __shared__ float sm3[64], sh[32];
    int n = blockIdx.x, c = threadIdx.x;
    const float* m = &g_meanV[(n * 64 + c) * 512];
    const float* gt = &g_gt[n * 512];
    float a = 0;
    for (int t = 0; t < 512; t++) a += m[t] * gt[t];
    sm3[c] = a * (1.f / 512.f);
    __syncthreads();
    if (c < 32) {
        float h = f1b[c];
        for (int k = 0; k < 64; k++) h += f1w[c * 64 + k] * sm3[k];
        sh[c] = fmaxf(h, 0.f);
    }
    __syncthreads();
    float o = f2b[c];
    for (int j = 0; j < 32; j++) o += f2w[c * 32 + j] * sh[j];
    g_gc[n * 64 + c] = 1.f + 1.f / (1.f + expf(-o));
}

// ---------------- TCN via mma.sync bf16-split + BN2 partial epilogue ----------------
// Retiled: each warp owns fixed n-group (ng = wid&3) so B fragments load once per (tap,ks)
// and are reused across its 3-4 strided m-tiles.
#define TCN_SMEM 189440
__global__ void __launch_bounds__(512) k_tcn() {
    extern __shared__ char smemraw[];
    __nv_bfloat16* Ah = (__nv_bfloat16*)smemraw;                 // [408][72]
    __nv_bfloat16* Wh = (__nv_bfloat16*)(smemraw + 117504);      // [64][72]
    __nv_bfloat16* Wl = (__nv_bfloat16*)(smemraw + 126720);
    float* zout = (float*)(smemraw + 135936);                    // [64][209]
    __shared__ float gsg[25], gtg[17], gcg[64];
    int tcb = blockIdx.x, n = blockIdx.y;
    int t0 = tcb * 8, tid = threadIdx.x;
    int wid = tid >> 5, lane = tid & 31;

    if (tid < 25) gsg[tid] = g_gs[n * 25 + tid];
    if (tid >= 32 && tid < 49) {
        int tin = t0 - 4 + (tid - 32);
        gtg[tid - 32] = (tin >= 0 && tin < 512) ? g_gt[n * 512 + tin] : 0.f;
    }
    if (tid >= 64 && tid < 128) gcg[tid - 64] = g_gc[n * 64 + (tid - 64)];
    __syncthreads();

    for (int idx = tid; idx < 408 * 64; idx += 512) {
        int c = idx / 408, s = idx - c * 408;
        int tvg = (t0 - 4) * 25 + s;
        float val = 0.f;
        if (tvg >= 0 && tvg < 12800)
            val = g_y2[(size_t)(n * 64 + c) * 12800 + tvg] * gsg[s % 25] * gtg[s / 25] * gcg[c];
        __nv_bfloat16 h = __float2bfloat16(val);
        Ah[s * 72 + c] = h;
        Ah[29376 + s * 72 + c] = __float2bfloat16(val - __bfloat162float(h));
    }

    // warp -> fixed n-group, strided m-tiles
    int ng = wid & 3, w4 = wid >> 2;
    int nbase = ng * 16;
    int mt[4], cnt = 0;
    for (int m = w4; m < 13; m += 4) mt[cnt++] = m;
    float acc[4][8];
#pragma unroll
    for (int q = 0; q < 4; q++)
#pragma unroll
        for (int i = 0; i < 8; i++) acc[q][i] = 0.f;

    unsigned baseA = su32(Ah), baseW = su32(Wh);
    int arow = lane & 15, acol8 = (lane >> 4) << 3;

    for (int tap = 0; tap < 9; tap++) {
        __syncthreads();
        for (int idx = tid; idx < 4608; idx += 512) {
            Wh[idx] = g_Wt9h[tap * 4608 + idx];
            Wl[idx] = g_Wt9l[tap * 4608 + idx];
        }
        __syncthreads();
#pragma unroll
        for (int ks = 0; ks < 4; ks++) {
            int c0 = ks * 16;
            unsigned bh[4], bl[4];
            unsigned baddr = baseW + (unsigned)(((c0 + arow) * 72 + nbase + acol8) * 2);
            ldsm4t(baddr, bh);
            ldsm4t(baddr + 9216u, bl);
#pragma unroll
            for (int q = 0; q < 4; q++) {
                if (q >= cnt) break;
                int rb = mt[q] * 16 + 25 * tap;
                unsigned aaddr = baseA + (unsigned)(((rb + arow) * 72 + c0 + acol8) * 2);
                unsigned ah[4], al[4];
                ldsm4(aaddr, ah);
                ldsm4(aaddr + 58752u, al);
                mma16816(&acc[q][0], ah, &bh[0]);
                mma16816(&acc[q][0], ah, &bl[0]);
                mma16816(&acc[q][0], al, &bh[0]);
                mma16816(&acc[q][4], ah, &bh[2]);
                mma16816(&acc[q][4], ah, &bl[2]);
                mma16816(&acc[q][4], al, &bh[2]);
            }
        }
    }
    __syncthreads();
#pragma unroll
    for (int q = 0; q < 4; q++) {
        if (q >= cnt) break;
#pragma unroll
        for (int h = 0; h < 2; h++) {
            int o0 = nbase + h * 8 + ((lane & 3) << 1);
            int r0 = mt[q] * 16 + (lane >> 2);
            zout[o0 * 209 + r0] = acc[q][h * 4 + 0];
            zout[(o0 + 1) * 209 + r0] = acc[q][h * 4 + 1];
            zout[o0 * 209 + r0 + 8] = acc[q][h * 4 + 2];
            zout[(o0 + 1) * 209 + r0 + 8] = acc[q][h * 4 + 3];
        }
    }
    __syncthreads();
    for (int idx = tid; idx < 64 * 200; idx += 512) {
        int o = idx / 200, sl = idx - o * 200;
        g_y[((size_t)(n * 64 + o) * 512 + t0) * 25 + sl] = zout[o * 209 + sl];
    }
    float* red = (float*)Wh;
    {
        int o = tid >> 3, sub = tid & 7;
        float a = 0, b = 0;
        for (int sl = sub; sl < 200; sl += 8) {
            float v = zout[o * 209 + sl];
            a += v; b += v * v;
        }
        red[tid] = a; red[512 + tid] = b;
    }
    __syncthreads();
    if (tid < 64) {
        float a = 0, b = 0;
        for (int p = 0; p < 8; p++) { a += red[tid * 8 + p]; b += red[512 + tid * 8 + p]; }
        g_bnS[(size_t)tid * 8192 + n * 64 + tcb] = a;
        g_bnQ[(size_t)tid * 8192 + n * 64 + tcb] = b;
    }
}

// final: out = relu(bn2(g_y) + x), vectorized
__global__ void __launch_bounds__(256) k_bnapply2(
    const float* __restrict__ gm, const float* __restrict__ bt,
    const float* __restrict__ x, float* __restrict__ out)
{
    size_t i4 = (size_t)blockIdx.x * 256 + threadIdx.x;
    size_t flat = i4 * 4;
    int c = (int)((flat / 12800) % 64);
    float m = g_stats[128 + c], r = g_stats[192 + c];
    float sc = r * gm[c];
    float sb = bt[c] - m * sc;
    float4 Y = *(const float4*)&g_y[flat];
    float4 X = *(const float4*)&x[flat];
    float4 O;
    O.x = fmaxf(Y.x * sc + sb + X.x, 0.f);
    O.y = fmaxf(Y.y * sc + sb + X.y, 0.f);
    O.z = fmaxf(Y.z * sc + sb + X.z, 0.f);
    O.w = fmaxf(Y.w * sc + sb + X.w, 0.f);
    *(float4*)&out[flat] = O;
}

// ---------------- launcher ----------------
extern "C" void kernel_launch(void* const* d_in, const int* in_sizes, int n_in,
                              void* d_out, int out_size) {
    const float* x   = (const float*)d_in[0];
    const float* PA  = (const float*)d_in[1];
    const float* alp = (const float*)d_in[2];
    const float* Wa  = (const float*)d_in[3];
    const float* ba  = (const float*)d_in[4];
    const float* Wb  = (const float*)d_in[5];
    const float* bb  = (const float*)d_in[6];
    const float* Wd  = (const float*)d_in[7];
    const float* bng = (const float*)d_in[9];
    const float* bnb = (const float*)d_in[10];
    const float* saw = (const float*)d_in[11];
    const float* sab = (const float*)d_in[12];
    const float* taw = (const float*)d_in[13];
    const float* tab = (const float*)d_in[14];
    const float* f1w = (const float*)d_in[15];
    const float* f1b = (const float*)d_in[16];
    const float* f2w = (const float*)d_in[17];
    const float* f2b = (const float*)d_in[18];
    const float* tw  = (const float*)d_in[19];
    const float* tbg = (const float*)d_in[21];
    const float* tbb = (const float*)d_in[22];
    float* out = (float*)d_out;

    cudaFuncSetAttribute(k_fabgram, cudaFuncAttributeMaxDynamicSharedMemorySize, 106880);
    cudaFuncSetAttribute(k_gcn, cudaFuncAttributeMaxDynamicSharedMemorySize, 75056);
    cudaFuncSetAttribute(k_tcn, cudaFuncAttributeMaxDynamicSharedMemorySize, TCN_SMEM);

    k_prep<<<64, 256>>>(Wd, tw);
    k_fabgram<<<dim3(64, 8), 256, 106880>>>(x, Wa, ba, Wb, bb);
    k_gram2<<<192, 256>>>(PA, alp);
    k_gcn<<<dim3(128, 64), 256, 75056>>>(x);
    k_bnfin<<<64, 256>>>(8192, 0);
    k_bnapply_mt<<<4096, 256>>>(bng, bnb, x);
    k_sattn<<<64, 32>>>(saw, sab);
    k_meanV<<<4096, 256>>>();
    k_tattn<<<64, 256>>>(taw, tab);
    k_cse<<<64, 64>>>(f1w, f1b, f2w, f2b);
    k_tcn<<<dim3(64, 64), 512, TCN_SMEM>>>();
    k_bnfin<<<64, 256>>>(4096, 128);
    k_bnapply2<<<51200, 256>>>(tbg, tbb, x, out);
}

// round 9
// speedup vs baseline: 1.1941x; 1.1144x over previous
#include <cuda_runtime.h>
#include <cuda_bf16.h>
#include <cstdint>
#include <math.h>

// dims: N=64, C=64, T=512, V=25, S=3, I=16
// ---------------- device scratch (no cudaMalloc allowed) ----------------
__device__ float g_Apart[1536u * 1024u];      // [(n*3+s)*8+seg][v32*32]
__device__ float g_Aeff[192 * 625];           // [n*3+s][v][w]
__device__ __nv_bfloat16 g_Wd2h[192 * 72];    // [k=s*64+c][o pad72] bf16 hi
__device__ __nv_bfloat16 g_Wd2l[192 * 72];    // bf16 lo
__device__ __nv_bfloat16 g_Wt9h[9 * 64 * 72]; // [k][c][o pad72] bf16 hi
__device__ __nv_bfloat16 g_Wt9l[9 * 64 * 72]; // bf16 lo
__device__ __nv_bfloat16 g_zh[157286400u];    // [n][slot=12800][k=192] bf16 hi
__device__ __nv_bfloat16 g_zl[157286400u];    // bf16 lo
__device__ float g_y[52428800u];              // pre-BN y; later reused for TCN z
__device__ float g_y2[52428800u];             // post BN1+residual+relu
__device__ float g_bnS[64u * 8192u];
__device__ float g_bnQ[64u * 8192u];
__device__ float g_stats[256];                // [off+c]=mean, [off+64+c]=rstd
__device__ float g_meanT[64 * 64 * 25];
__device__ float g_gs[64 * 25];               // 1+sigmoid spatial gate
__device__ float g_meanV[64 * 64 * 512];
__device__ float g_gt[64 * 512];              // 1+sigmoid temporal gate
__device__ float g_gc[64 * 64];               // 1+sigmoid channel gate

// ---------------- mma helpers ----------------
__device__ __forceinline__ unsigned su32(const void* p) {
    return (unsigned)__cvta_generic_to_shared(p);
}
__device__ __forceinline__ void ldsm4(unsigned addr, unsigned* r) {
    asm volatile("ldmatrix.sync.aligned.m8n8.x4.shared.b16 {%0,%1,%2,%3}, [%4];"
                 : "=r"(r[0]), "=r"(r[1]), "=r"(r[2]), "=r"(r[3]) : "r"(addr));
}
__device__ __forceinline__ void ldsm4t(unsigned addr, unsigned* r) {
    asm volatile("ldmatrix.sync.aligned.m8n8.x4.trans.shared.b16 {%0,%1,%2,%3}, [%4];"
                 : "=r"(r[0]), "=r"(r[1]), "=r"(r[2]), "=r"(r[3]) : "r"(addr));
}
__device__ __forceinline__ void mma16816(float* d, const unsigned* a, const unsigned* b) {
    asm volatile("mma.sync.aligned.m16n8k16.row.col.f32.bf16.bf16.f32 "
                 "{%0,%1,%2,%3}, {%4,%5,%6,%7}, {%8,%9}, {%0,%1,%2,%3};"
                 : "+f"(d[0]), "+f"(d[1]), "+f"(d[2]), "+f"(d[3])
                 : "r"(a[0]), "r"(a[1]), "r"(a[2]), "r"(a[3]), "r"(b[0]), "r"(b[1]));
}
// pack two floats into bf16x2 hi-plane and lo-plane words
__device__ __forceinline__ void split2(float a, float b, unsigned& uh, unsigned& ul) {
    __nv_bfloat16 ha = __float2bfloat16(a), hb = __float2bfloat16(b);
    __nv_bfloat16 la = __float2bfloat16(a - __bfloat162float(ha));
    __nv_bfloat16 lb = __float2bfloat16(b - __bfloat162float(hb));
    uh = ((unsigned)__bfloat16_as_ushort(hb) << 16) | __bfloat16_as_ushort(ha);
    ul = ((unsigned)__bfloat16_as_ushort(lb) << 16) | __bfloat16_as_ushort(la);
}

// ---------------- weight prep ----------------
__global__ void k_prep(const float* __restrict__ Wd, const float* __restrict__ tw) {
    int tid = blockIdx.x * 256 + threadIdx.x;
    int stride = gridDim.x * 256;
    // GCN stage2 weights, B-side layout [k][o pad72]
    for (int i = tid; i < 192 * 72; i += stride) {
        int k = i / 72, o = i % 72;
        float w = 0.f;
        if (o < 64) { int s = k >> 6, c = k & 63; w = Wd[s * 4096 + o * 64 + c]; }
        __nv_bfloat16 h = __float2bfloat16(w);
        g_Wd2h[i] = h;
        g_Wd2l[i] = __float2bfloat16(w - __bfloat162float(h));
    }
    // bf16 split TCN weights: [k][c][o pad 72]
    for (int i = tid; i < 9 * 64 * 72; i += stride) {
        int k = i / 4608, r = i % 4608, c = r / 72, o = r % 72;
        float w = (o < 64) ? tw[o * 576 + c * 9 + k] : 0.f;
        __nv_bfloat16 h = __float2bfloat16(w);
        g_Wt9h[i] = h;
        g_Wt9l[i] = __float2bfloat16(w - __bfloat162float(h));
    }
}

// ---------------- fused fa/fb projection + Gram partials ----------------
__global__ void __launch_bounds__(256) k_fabgram(
    const float* __restrict__ x, const float* __restrict__ Wa, const float* __restrict__ ba,
    const float* __restrict__ Wb, const float* __restrict__ bb)
{
    extern __shared__ float sm[];
    float* xs  = sm;                 // [c=64][4t*32v] = 8192
    float* Wab = sm + 8192;          // [s*32+r][stride65] = 6240
    float* fs  = sm + 8192 + 6240;   // [(s*2+side)][64k][32v] = 12288
    int n = blockIdx.x, seg = blockIdx.y, tid = threadIdx.x;
    int tseg0 = seg * 64;

    for (int idx = tid; idx < 3 * 32 * 64; idx += 256) {
        int s = idx / 2048, r = (idx / 64) % 32, c = idx % 64;
        float w = (r < 16) ? Wa[s * 1024 + r * 64 + c] : Wb[s * 1024 + (r - 16) * 64 + c];
        Wab[(s * 32 + r) * 65 + c] = w;
    }
    int ig = tid & 7;
    int vq = (tid >> 3) & 7;
    int tloc = tid >> 6;

    float bias[3][4];
#pragma unroll
    for (int s = 0; s < 3; s++)
#pragma unroll
        for (int j = 0; j < 4; j++) {
            int r = ig * 4 + j;
            bias[s][j] = (r < 16) ? ba[s * 16 + r] : bb[s * 16 + (r - 16)];
        }
    int side = ig >> 2;
    int gv = tid >> 3, gw4 = (tid & 7) * 4;

    float gacc[3][4];
#pragma unroll
    for (int s = 0; s < 3; s++)
#pragma unroll
        for (int q = 0; q < 4; q++) gacc[s][q] = 0.f;

    for (int sub = 0; sub < 16; sub++) {
        int t0 = tseg0 + sub * 4;
        for (int idx = tid; idx < 8192; idx += 256) {
            int c = idx >> 7, r = idx & 127, t = r >> 5, v = r & 31;
            xs[idx] = (v < 25) ? x[(((size_t)n * 64 + c) * 512 + t0 + t) * 25 + v] : 0.f;
        }
        __syncthreads();
        float4 facc[3][4];
#pragma unroll
        for (int s = 0; s < 3; s++)
#pragma unroll
            for (int j = 0; j < 4; j++) {
                float b0 = bias[s][j];
                facc[s][j] = make_float4(b0, b0, b0, b0);
            }
        for (int c = 0; c < 64; c++) {
            float4 X = *(const float4*)&xs[c * 128 + tloc * 32 + vq * 4];
#pragma unroll
            for (int s = 0; s < 3; s++)
#pragma unroll
                for (int j = 0; j < 4; j++) {
                    float w = Wab[(s * 32 + ig * 4 + j) * 65 + c];
                    facc[s][j].x += w * X.x; facc[s][j].y += w * X.y;
                    facc[s][j].z += w * X.z; facc[s][j].w += w * X.w;
                }
        }
#pragma unroll
        for (int s = 0; s < 3; s++)
#pragma unroll
            for (int j = 0; j < 4; j++) {
                int kl = tloc * 16 + (ig & 3) * 4 + j;
                *(float4*)&fs[(s * 2 + side) * 2048 + kl * 32 + vq * 4] = facc[s][j];
            }
        __syncthreads();
#pragma unroll
        for (int s = 0; s < 3; s++) {
            const float* fap = &fs[(s * 2 + 0) * 2048];
            const float* fbp = &fs[(s * 2 + 1) * 2048];
            for (int kk = 0; kk < 64; kk++) {
                float fav = fap[kk * 32 + gv];
                float4 f4 = *(const float4*)&fbp[kk * 32 + gw4];
                gacc[s][0] += fav * f4.x; gacc[s][1] += fav * f4.y;
                gacc[s][2] += fav * f4.z; gacc[s][3] += fav * f4.w;
            }
        }
        __syncthreads();
    }
#pragma unroll
    for (int s = 0; s < 3; s++) {
        float* p = &g_Apart[((size_t)((n * 3 + s) * 8 + seg)) * 1024 + gv * 32 + gw4];
        p[0] = gacc[s][0]; p[1] = gacc[s][1]; p[2] = gacc[s][2]; p[3] = gacc[s][3];
    }
}

__global__ void k_gram2(const float* __restrict__ PA, const float* __restrict__ alpha) {
    int ns = blockIdx.x; int s = ns % 3;
    float al = alpha[0];
    for (int p = threadIdx.x; p < 625; p += 256) {
        int v = p / 25, w = p % 25;
        float sum = 0;
        for (int seg = 0; seg < 8; seg++)
            sum += g_Apart[((size_t)ns * 8 + seg) * 1024 + v * 32 + w];
        float A1 = tanhf(sum * (1.0f / 8192.0f));
        g_Aeff[ns * 625 + p] = PA[s * 625 + p] + al * A1;
    }
}

// ---------------- GCN stage1: z[slot][k] = x·Ae, bf16 split to gmem ----------------
// grid (64 tchunk of 8t, 64 n), 256 thr, 2 CTAs/SM. Thread = (c-oct, w).
#define GCN1_SMEM 82800
__global__ void __launch_bounds__(256, 2) k_gcn1(const float* __restrict__ x) {
    extern __shared__ char s1raw[];
    float* xT = (float*)s1raw;                       // [tv=200][68c] 54400B
    float* ae = (float*)(s1raw + 54400);             // [3][25][28]   8400B
    __nv_bfloat16* Zth = (__nv_bfloat16*)(s1raw + 62800);  // [25w][200k] 10000B
    __nv_bfloat16* Ztl = (__nv_bfloat16*)(s1raw + 72800);  // 10000B
    int tcb = blockIdx.x, n = blockIdx.y;
    int t0 = tcb * 8, tid = threadIdx.x;

    for (int idx = tid; idx < 12800; idx += 256) {
        int c = idx / 200, tv = idx % 200;
        xT[tv * 68 + c] = x[(((size_t)n * 64 + c) * 512 + t0 + tv / 25) * 25 + tv % 25];
    }
    for (int idx = tid; idx < 2100; idx += 256) {
        int s = idx / 700, r = idx % 700, v = r / 28, w = r % 28;
        ae[idx] = (w < 25) ? g_Aeff[(size_t)(n * 3 + s) * 625 + v * 25 + w] : 0.f;
    }
    __syncthreads();

    int co = (tid & 7) * 8, w = tid >> 3;   // w 0..31, active if <25
    unsigned* zh32 = (unsigned*)g_zh;
    unsigned* zl32 = (unsigned*)g_zl;
    const unsigned* th32 = (const unsigned*)Zth;
    const unsigned* tl32 = (const unsigned*)Ztl;

    for (int t = 0; t < 8; t++) {
        if (w < 25) {
            float acc[3][8];
#pragma unroll
            for (int s = 0; s < 3; s++)
#pragma unroll
                for (int i = 0; i < 8; i++) acc[s][i] = 0.f;
            for (int v = 0; v < 25; v++) {
                float4 X0 = *(const float4*)&xT[(t * 25 + v) * 68 + co];
                float4 X1 = *(const float4*)&xT[(t * 25 + v) * 68 + co + 4];
#pragma unroll
                for (int s = 0; s < 3; s++) {
                    float e = ae[s * 700 + v * 28 + w];
                    acc[s][0] += X0.x * e; acc[s][1] += X0.y * e;
                    acc[s][2] += X0.z * e; acc[s][3] += X0.w * e;
                    acc[s][4] += X1.x * e; acc[s][5] += X1.y * e;
                    acc[s][6] += X1.z * e; acc[s][7] += X1.w * e;
                }
            }
#pragma unroll
            for (int s = 0; s < 3; s++)
#pragma unroll
                for (int j = 0; j < 4; j++) {
                    unsigned uh, ul;
                    split2(acc[s][2 * j], acc[s][2 * j + 1], uh, ul);
                    int k = s * 64 + co + 2 * j;
                    *(unsigned*)&Zth[w * 200 + k] = uh;
                    *(unsigned*)&Ztl[w * 200 + k] = ul;
                }
        }
        __syncthreads();
        size_t sbase = (size_t)n * 12800 + (size_t)(t0 + t) * 25;
        for (int idx = tid; idx < 2400; idx += 256) {
            int ww = idx / 96, kp = idx % 96;
            size_t d = (sbase + ww) * 96 + kp;
            zh32[d] = th32[ww * 100 + kp];
            zl32[d] = tl32[ww * 100 + kp];
        }
        __syncthreads();
    }
}

// ---------------- GCN stage2: y[o][slot] = Wd2[k][o]^T · z[slot][k], MMA + BN1 ----------------
// grid (100 slot-chunks of 128, 64 n), 512 thr.
#define GCN2_SMEM 192512
__global__ void __launch_bounds__(512) k_gcn2() {
    extern __shared__ char s2raw[];
    __nv_bfloat16* Azh = (__nv_bfloat16*)s2raw;              // [128][200] 51200B
    __nv_bfloat16* Wh = (__nv_bfloat16*)(s2raw + 102400);    // [192][72]  27648B
    float* zout = (float*)(s2raw + 157696);                  // [64][136]  34816B
    int blk = blockIdx.x, n = blockIdx.y;
    int slot0 = blk * 128, tid = threadIdx.x;
    int wid = tid >> 5, lane = tid & 31;

    // stage A (z tile) hi/lo
    {
        unsigned* dh = (unsigned*)s2raw;
        unsigned* dl = (unsigned*)(s2raw + 51200);
        const unsigned* shp = (const unsigned*)g_zh;
        const unsigned* slp = (const unsigned*)g_zl;
        for (int idx = tid; idx < 12288; idx += 512) {
            int row = idx / 96, kp = idx % 96;
            size_t src = ((size_t)n * 12800 + slot0 + row) * 96 + kp;
            dh[row * 100 + kp] = shp[src];
            dl[row * 100 + kp] = slp[src];
        }
    }
    // stage W hi/lo
    {
        unsigned* dh = (unsigned*)(s2raw + 102400);
        unsigned* dl = (unsigned*)(s2raw + 130048);
        const unsigned* shp = (const unsigned*)g_Wd2h;
        const unsigned* slp = (const unsigned*)g_Wd2l;
        for (int idx = tid; idx < 6912; idx += 512) { dh[idx] = shp[idx]; dl[idx] = slp[idx]; }
    }
    __syncthreads();

    int ng = wid & 3, m0 = wid >> 2;  // tiles m0, m0+4; n-group fixed
    float acc[2][8];
#pragma unroll
    for (int q = 0; q < 2; q++)
#pragma unroll
        for (int i = 0; i < 8; i++) acc[q][i] = 0.f;

    unsigned baseA = su32(Azh), baseW = su32(Wh);
    int arow = lane & 15, acol8 = (lane >> 4) << 3;
#pragma unroll
    for (int ks = 0; ks < 12; ks++) {
        int k0 = ks * 16;
        unsigned bh[4], bl[4];
        unsigned baddr = baseW + (unsigned)(((k0 + arow) * 72 + ng * 16 + acol8) * 2);
        ldsm4t(baddr, bh);
        ldsm4t(baddr + 27648u, bl);
#pragma unroll
        for (int q = 0; q < 2; q++) {
            int mt = m0 + q * 4;
            unsigned aaddr = baseA + (unsigned)(((mt * 16 + arow) * 200 + k0 + acol8) * 2);
            unsigned ah[4], al[4];
            ldsm4(aaddr, ah);
            ldsm4(aaddr + 51200u, al);
            mma16816(&acc[q][0], ah, &bh[0]);
            mma16816(&acc[q][0], ah, &bl[0]);
            mma16816(&acc[q][0], al, &bh[0]);
            mma16816(&acc[q][4], ah, &bh[2]);
            mma16816(&acc[q][4], ah, &bl[2]);
            mma16816(&acc[q][4], al, &bh[2]);
        }
    }
    __syncthreads();   // A region reuse below; MMA reads done
#pragma unroll
    for (int q = 0; q < 2; q++) {
        int r0 = (m0 + q * 4) * 16 + (lane >> 2);
#pragma unroll
        for (int h = 0; h < 2; h++) {
            int o0 = ng * 16 + h * 8 + ((lane & 3) << 1);
            zout[o0 * 136 + r0] = acc[q][h * 4 + 0];
            zout[(o0 + 1) * 136 + r0] = acc[q][h * 4 + 1];
            zout[o0 * 136 + r0 + 8] = acc[q][h * 4 + 2];
            zout[(o0 + 1) * 136 + r0 + 8] = acc[q][h * 4 + 3];
        }
    }
    __syncthreads();
    for (int idx = tid; idx < 8192; idx += 512) {
        int o = idx / 128, sl = idx % 128;
        g_y[(size_t)(n * 64 + o) * 12800 + slot0 + sl] = zout[o * 136 + sl];
    }
    // BN1 partials
    float* red = (float*)s2raw;
    {
        int o = tid >> 3, sub = tid & 7;
        float a = 0, b = 0;
        for (int sl = sub; sl < 128; sl += 8) {
            float v = zout[o * 136 + sl];
            a += v; b += v * v;
        }
        red[tid] = a; red[512 + tid] = b;
    }
    __syncthreads();
    if (tid < 64) {
        float a = 0, b = 0;
        for (int p = 0; p < 8; p++) { a += red[tid * 8 + p]; b += red[512 + tid * 8 + p]; }
        g_bnS[(size_t)tid * 8192 + n * 100 + blk] = a;
        g_bnQ[(size_t)tid * 8192 + n * 100 + blk] = b;
    }
}

__global__ void k_bnfin(int cnt, int off) {
    __shared__ float s1[256], s2[256];
    int c = blockIdx.x, tid = threadIdx.x;
    float a = 0, b = 0;
    for (int i = tid; i < cnt; i += 256) {
        a += g_bnS[(size_t)c * 8192 + i];
        b += g_bnQ[(size_t)c * 8192 + i];
    }
    s1[tid] = a; s2[tid] = b; __syncthreads();
    for (int st = 128; st > 0; st >>= 1) {
        if (tid < st) { s1[tid] += s1[tid + st]; s2[tid] += s2[tid + st]; }
        __syncthreads();
    }
    if (tid == 0) {
        float m = s1[0] / 819200.0f;
        float v = s2[0] / 819200.0f - m * m;
        g_stats[off + c] = m;
        g_stats[off + 64 + c] = rsqrtf(v + 1e-5f);
    }
}

// BN1 apply + residual + relu -> g_y2, fused T-mean partials -> g_meanT
__global__ void __launch_bounds__(256) k_bnapply_mt(
    const float* __restrict__ gm, const float* __restrict__ bt, const float* __restrict__ x)
{
    __shared__ float red[8 * 33];
    int nc = blockIdx.x, tid = threadIdx.x, lane = tid & 31, tg = tid >> 5;
    int c = nc & 63;
    float m = g_stats[c], r = g_stats[64 + c];
    float sc = r * gm[c], sb = bt[c] - m * sc;
    float a = 0;
    if (lane < 25) {
        size_t base = (size_t)nc * 12800 + lane;
        for (int t = tg; t < 512; t += 8) {
            float y = g_y[base + t * 25];
            float o = fmaxf(y * sc + sb + x[base + t * 25], 0.f);
            g_y2[base + t * 25] = o;
            a += o;
        }
        red[tg * 33 + lane] = a;
    }
    __syncthreads();
    if (tid < 25) {
        float s = 0;
        for (int g = 0; g < 8; g++) s += red[g * 33 + tid];
        g_meanT[nc * 25 + tid] = s * (1.f / 512.f);
    }
}

// ---------------- attention chain ----------------
__global__ void k_sattn(const float* __restrict__ saw, const float* __restrict__ sab) {
    int n = blockIdx.x, v = threadIdx.x;
    if (v < 25) {
        float acc = sab[0];
        for (int c = 0; c < 64; c++) {
            const float* m = &g_meanT[(n * 64 + c) * 25];
            const float* w = &saw[c * 25];
#pragma unroll
            for (int j = 0; j < 25; j++) {
                int vv = v + j - 12;
                if (vv >= 0 && vv < 25) acc += w[j] * m[vv];
            }
        }
        g_gs[n * 25 + v] = 1.f + 1.f / (1.f + expf(-acc));
    }
}

__global__ void __launch_bounds__(256) k_meanV() {
    __shared__ float sgs[25];
    int nc = blockIdx.x, tid = threadIdx.x;
    int n = nc >> 6;
    if (tid < 25) sgs[tid] = g_gs[n * 25 + tid];
    __syncthreads();
    for (int t = tid; t < 512; t += 256) {
        const float* row = &g_y2[(size_t)nc * 12800 + t * 25];
        float a = 0;
#pragma unroll
        for (int v = 0; v < 25; v++) a += row[v] * sgs[v];
        g_meanV[nc * 512 + t] = a * (1.f / 25.f);
    }
}

__global__ void k_tattn(const float* __restrict__ taw, const float* __restrict__ tab) {
    int n = blockIdx.x, tid = threadIdx.x;
    for (int t = tid; t < 512; t += 256) {
        float acc = tab[0];
        for (int c = 0; c < 64; c++) {
            const float* m = &g_meanV[(n * 64 + c) * 512];
            const float* w = &taw[c * 9];
#pragma unroll
            for (int j = 0; j < 9; j++) {
                int tt = t + j - 4;
                if (tt >= 0 && tt < 512) acc += w[j] * m[tt];
            }
        }
        g_gt[n * 512 + t] = 1.f + 1.f / (1.f + expf(-acc));
    }
}

__global__ void k_cse(const float* __restrict__ f1w, const float* __restrict__ f1b,
                      const float* __restrict__ f2w, const float* __restrict__ f2b) {
    __shared__ float sm3[64], sh[32];
    int n = blockIdx.x, c = threadIdx.x;
    const float* m = &g_meanV[(n * 64 + c) * 512];
    const float* gt = &g_gt[n * 512];
    float a = 0;
    for (int t = 0; t < 512; t++) a += m[t] * gt[t];
    sm3[c] = a * (1.f / 512.f);
    __syncthreads();
    if (c < 32) {
        float h = f1b[c];
        for (int k = 0; k < 64; k++) h += f1w[c * 64 + k] * sm3[k];
        sh[c] = fmaxf(h, 0.f);
    }
    __syncthreads();
    float o = f2b[c];
    for (int j = 0; j < 32; j++) o += f2w[c * 32 + j] * sh[j];
    g_gc[n * 64 + c] = 1.f + 1.f / (1.f + expf(-o));
}

// ---------------- TCN via mma.sync bf16-split + BN2 partial epilogue ----------------
#define TCN_SMEM 189440
__global__ void __launch_bounds__(512) k_tcn() {
    extern __shared__ char smemraw[];
    __nv_bfloat16* Ah = (__nv_bfloat16*)smemraw;                 // [408][72]
    __nv_bfloat16* Wh = (__nv_bfloat16*)(smemraw + 117504);      // [64][72]
    __nv_bfloat16* Wl = (__nv_bfloat16*)(smemraw + 126720);
    float* zout = (float*)(smemraw + 135936);                    // [64][209]
    __shared__ float gsg[25], gtg[17], gcg[64];
    int tcb = blockIdx.x, n = blockIdx.y;
    int t0 = tcb * 8, tid = threadIdx.x;
    int wid = tid >> 5, lane = tid & 31;

    if (tid < 25) gsg[tid] = g_gs[n * 25 + tid];
    if (tid >= 32 && tid < 49) {
        int tin = t0 - 4 + (tid - 32);
        gtg[tid - 32] = (tin >= 0 && tin < 512) ? g_gt[n * 512 + tin] : 0.f;
    }
    if (tid >= 64 && tid < 128) gcg[tid - 64] = g_gc[n * 64 + (tid - 64)];
    __syncthreads();

    // vectorized staging: thread handles a c-pair at one s
    for (int idx = tid; idx < 408 * 32; idx += 512) {
        int cp = idx / 408, s = idx - cp * 408;
        int tvg = (t0 - 4) * 25 + s;
        float v0 = 0.f, v1 = 0.f;
        if (tvg >= 0 && tvg < 12800) {
            float g = gsg[s % 25] * gtg[s / 25];
            v0 = g_y2[(size_t)(n * 64 + 2 * cp) * 12800 + tvg] * g * gcg[2 * cp];
            v1 = g_y2[(size_t)(n * 64 + 2 * cp + 1) * 12800 + tvg] * g * gcg[2 * cp + 1];
        }
        unsigned uh, ul;
        split2(v0, v1, uh, ul);
        *(unsigned*)&Ah[s * 72 + 2 * cp] = uh;
        *(unsigned*)&Ah[29376 + s * 72 + 2 * cp] = ul;
    }

    // warp -> fixed n-group, strided m-tiles
    int ng = wid & 3, w4 = wid >> 2;
    int nbase = ng * 16;
    int mt[4], cnt = 0;
    for (int m = w4; m < 13; m += 4) mt[cnt++] = m;
    float acc[4][8];
#pragma unroll
    for (int q = 0; q < 4; q++)
#pragma unroll
        for (int i = 0; i < 8; i++) acc[q][i] = 0.f;

    unsigned baseA = su32(Ah), baseW = su32(Wh);
    int arow = lane & 15, acol8 = (lane >> 4) << 3;

    for (int tap = 0; tap < 9; tap++) {
        __syncthreads();
        for (int idx = tid; idx < 4608; idx += 512) {
            Wh[idx] = g_Wt9h[tap * 4608 + idx];
            Wl[idx] = g_Wt9l[tap * 4608 + idx];
        }
        __syncthreads();
#pragma unroll
        for (int ks = 0; ks < 4; ks++) {
            int c0 = ks * 16;
            unsigned bh[4], bl[4];
            unsigned baddr = baseW + (unsigned)(((c0 + arow) * 72 + nbase + acol8) * 2);
            ldsm4t(baddr, bh);
            ldsm4t(baddr + 9216u, bl);
#pragma unroll
            for (int q = 0; q < 4; q++) {
                if (q >= cnt) break;
                int rb = mt[q] * 16 + 25 * tap;
                unsigned aaddr = baseA + (unsigned)(((rb + arow) * 72 + c0 + acol8) * 2);
                unsigned ah[4], al[4];
                ldsm4(aaddr, ah);
                ldsm4(aaddr + 58752u, al);
                mma16816(&acc[q][0], ah, &bh[0]);
                mma16816(&acc[q][0], ah, &bl[0]);
                mma16816(&acc[q][0], al, &bh[0]);
                mma16816(&acc[q][4], ah, &bh[2]);
                mma16816(&acc[q][4], ah, &bl[2]);
                mma16816(&acc[q][4], al, &bh[2]);
            }
        }
    }
    __syncthreads();
#pragma unroll
    for (int q = 0; q < 4; q++) {
        if (q >= cnt) break;
#pragma unroll
        for (int h = 0; h < 2; h++) {
            int o0 = nbase + h * 8 + ((lane & 3) << 1);
            int r0 = mt[q] * 16 + (lane >> 2);
            zout[o0 * 209 + r0] = acc[q][h * 4 + 0];
            zout[(o0 + 1) * 209 + r0] = acc[q][h * 4 + 1];
            zout[o0 * 209 + r0 + 8] = acc[q][h * 4 + 2];
            zout[(o0 + 1) * 209 + r0 + 8] = acc[q][h * 4 + 3];
        }
    }
    __syncthreads();
    for (int idx = tid; idx < 64 * 200; idx += 512) {
        int o = idx / 200, sl = idx - o * 200;
        g_y[((size_t)(n * 64 + o) * 512 + t0) * 25 + sl] = zout[o * 209 + sl];
    }
    float* red = (float*)Wh;
    {
        int o = tid >> 3, sub = tid & 7;
        float a = 0, b = 0;
        for (int sl = sub; sl < 200; sl += 8) {
            float v = zout[o * 209 + sl];
            a += v; b += v * v;
        }
        red[tid] = a; red[512 + tid] = b;
    }
    __syncthreads();
    if (tid < 64) {
        float a = 0, b = 0;
        for (int p = 0; p < 8; p++) { a += red[tid * 8 + p]; b += red[512 + tid * 8 + p]; }
        g_bnS[(size_t)tid * 8192 + n * 64 + tcb] = a;
        g_bnQ[(size_t)tid * 8192 + n * 64 + tcb] = b;
    }
}

// final: out = relu(bn2(g_y) + x), vectorized
__global__ void __launch_bounds__(256) k_bnapply2(
    const float* __restrict__ gm, const float* __restrict__ bt,
    const float* __restrict__ x, float* __restrict__ out)
{
    size_t i4 = (size_t)blockIdx.x * 256 + threadIdx.x;
    size_t flat = i4 * 4;
    int c = (int)((flat / 12800) % 64);
    float m = g_stats[128 + c], r = g_stats[192 + c];
    float sc = r * gm[c];
    float sb = bt[c] - m * sc;
    float4 Y = *(const float4*)&g_y[flat];
    float4 X = *(const float4*)&x[flat];
    float4 O;
    O.x = fmaxf(Y.x * sc + sb + X.x, 0.f);
    O.y = fmaxf(Y.y * sc + sb + X.y, 0.f);
    O.z = fmaxf(Y.z * sc + sb + X.z, 0.f);
    O.w = fmaxf(Y.w * sc + sb + X.w, 0.f);
    *(float4*)&out[flat] = O;
}

// ---------------- launcher ----------------
extern "C" void kernel_launch(void* const* d_in, const int* in_sizes, int n_in,
                              void* d_out, int out_size) {
    const float* x   = (const float*)d_in[0];
    const float* PA  = (const float*)d_in[1];
    const float* alp = (const float*)d_in[2];
    const float* Wa  = (const float*)d_in[3];
    const float* ba  = (const float*)d_in[4];
    const float* Wb  = (const float*)d_in[5];
    const float* bb  = (const float*)d_in[6];
    const float* Wd  = (const float*)d_in[7];
    const float* bng = (const float*)d_in[9];
    const float* bnb = (const float*)d_in[10];
    const float* saw = (const float*)d_in[11];
    const float* sab = (const float*)d_in[12];
    const float* taw = (const float*)d_in[13];
    const float* tab = (const float*)d_in[14];
    const float* f1w = (const float*)d_in[15];
    const float* f1b = (const float*)d_in[16];
    const float* f2w = (const float*)d_in[17];
    const float* f2b = (const float*)d_in[18];
    const float* tw  = (const float*)d_in[19];
    const float* tbg = (const float*)d_in[21];
    const float* tbb = (const float*)d_in[22];
    float* out = (float*)d_out;

    cudaFuncSetAttribute(k_fabgram, cudaFuncAttributeMaxDynamicSharedMemorySize, 106880);
    cudaFuncSetAttribute(k_gcn1, cudaFuncAttributeMaxDynamicSharedMemorySize, GCN1_SMEM);
    cudaFuncSetAttribute(k_gcn2, cudaFuncAttributeMaxDynamicSharedMemorySize, GCN2_SMEM);
    cudaFuncSetAttribute(k_tcn, cudaFuncAttributeMaxDynamicSharedMemorySize, TCN_SMEM);

    k_prep<<<64, 256>>>(Wd, tw);
    k_fabgram<<<dim3(64, 8), 256, 106880>>>(x, Wa, ba, Wb, bb);
    k_gram2<<<192, 256>>>(PA, alp);
    k_gcn1<<<dim3(64, 64), 256, GCN1_SMEM>>>(x);
    k_gcn2<<<dim3(100, 64), 512, GCN2_SMEM>>>();
    k_bnfin<<<64, 256>>>(6400, 0);
    k_bnapply_mt<<<4096, 256>>>(bng, bnb, x);
    k_sattn<<<64, 32>>>(saw, sab);
    k_meanV<<<4096, 256>>>();
    k_tattn<<<64, 256>>>(taw, tab);
    k_cse<<<64, 64>>>(f1w, f1b, f2w, f2b);
    k_tcn<<<dim3(64, 64), 512, TCN_SMEM>>>();
    k_bnfin<<<64, 256>>>(4096, 128);
    k_bnapply2<<<51200, 256>>>(tbg, tbb, x, out);
}

// round 10
// speedup vs baseline: 1.2310x; 1.0309x over previous
#include <cuda_runtime.h>
#include <cuda_bf16.h>
#include <cstdint>
#include <math.h>

// dims: N=64, C=64, T=512, V=25, S=3, I=16
// ---------------- device scratch (no cudaMalloc allowed) ----------------
__device__ float g_Apart[1536u * 1024u];      // [(n*3+s)*8+seg][v32*32]
__device__ float g_Aeff[192 * 625];           // [n*3+s][v][w]
__device__ __nv_bfloat16 g_Wd2h[192 * 72];    // [k=s*64+c][o pad72] bf16 hi
__device__ __nv_bfloat16 g_Wd2l[192 * 72];    // bf16 lo
__device__ __nv_bfloat16 g_Wt9h[9 * 64 * 72]; // [k][c][o pad72] bf16 hi
__device__ __nv_bfloat16 g_Wt9l[9 * 64 * 72]; // bf16 lo
__device__ __nv_bfloat16 g_zh[157286400u];    // [n][slot=12800][k=192] bf16 hi
__device__ __nv_bfloat16 g_zl[157286400u];    // bf16 lo
__device__ float g_y[52428800u];              // pre-BN y; later reused for TCN z
__device__ float g_y2[52428800u];             // post BN1+residual+relu
__device__ float g_bnS[64u * 8192u];
__device__ float g_bnQ[64u * 8192u];
__device__ float g_stats[256];                // [off+c]=mean, [off+64+c]=rstd
__device__ float g_meanT[64 * 64 * 25];
__device__ float g_gs[64 * 25];               // 1+sigmoid spatial gate
__device__ float g_meanV[64 * 64 * 512];
__device__ float g_gt[64 * 512];              // 1+sigmoid temporal gate
__device__ float g_gc[64 * 64];               // 1+sigmoid channel gate

// ---------------- mma helpers ----------------
__device__ __forceinline__ unsigned su32(const void* p) {
    return (unsigned)__cvta_generic_to_shared(p);
}
__device__ __forceinline__ void ldsm4(unsigned addr, unsigned* r) {
    asm volatile("ldmatrix.sync.aligned.m8n8.x4.shared.b16 {%0,%1,%2,%3}, [%4];"
                 : "=r"(r[0]), "=r"(r[1]), "=r"(r[2]), "=r"(r[3]) : "r"(addr));
}
__device__ __forceinline__ void ldsm4t(unsigned addr, unsigned* r) {
    asm volatile("ldmatrix.sync.aligned.m8n8.x4.trans.shared.b16 {%0,%1,%2,%3}, [%4];"
                 : "=r"(r[0]), "=r"(r[1]), "=r"(r[2]), "=r"(r[3]) : "r"(addr));
}
__device__ __forceinline__ void mma16816(float* d, const unsigned* a, const unsigned* b) {
    asm volatile("mma.sync.aligned.m16n8k16.row.col.f32.bf16.bf16.f32 "
                 "{%0,%1,%2,%3}, {%4,%5,%6,%7}, {%8,%9}, {%0,%1,%2,%3};"
                 : "+f"(d[0]), "+f"(d[1]), "+f"(d[2]), "+f"(d[3])
                 : "r"(a[0]), "r"(a[1]), "r"(a[2]), "r"(a[3]), "r"(b[0]), "r"(b[1]));
}
// pack two floats into bf16x2 hi-plane and lo-plane words
__device__ __forceinline__ void split2(float a, float b, unsigned& uh, unsigned& ul) {
    __nv_bfloat16 ha = __float2bfloat16(a), hb = __float2bfloat16(b);
    __nv_bfloat16 la = __float2bfloat16(a - __bfloat162float(ha));
    __nv_bfloat16 lb = __float2bfloat16(b - __bfloat162float(hb));
    uh = ((unsigned)__bfloat16_as_ushort(hb) << 16) | __bfloat16_as_ushort(ha);
    ul = ((unsigned)__bfloat16_as_ushort(lb) << 16) | __bfloat16_as_ushort(la);
}

// ---------------- weight prep ----------------
__global__ void k_prep(const float* __restrict__ Wd, const float* __restrict__ tw) {
    int tid = blockIdx.x * 256 + threadIdx.x;
    int stride = gridDim.x * 256;
    // GCN stage2 weights, B-side layout [k][o pad72]
    for (int i = tid; i < 192 * 72; i += stride) {
        int k = i / 72, o = i % 72;
        float w = 0.f;
        if (o < 64) { int s = k >> 6, c = k & 63; w = Wd[s * 4096 + o * 64 + c]; }
        __nv_bfloat16 h = __float2bfloat16(w);
        g_Wd2h[i] = h;
        g_Wd2l[i] = __float2bfloat16(w - __bfloat162float(h));
    }
    // bf16 split TCN weights: [k][c][o pad 72]
    for (int i = tid; i < 9 * 64 * 72; i += stride) {
        int k = i / 4608, r = i % 4608, c = r / 72, o = r % 72;
        float w = (o < 64) ? tw[o * 576 + c * 9 + k] : 0.f;
        __nv_bfloat16 h = __float2bfloat16(w);
        g_Wt9h[i] = h;
        g_Wt9l[i] = __float2bfloat16(w - __bfloat162float(h));
    }
}

// ---------------- fused fa/fb projection + Gram partials ----------------
__global__ void __launch_bounds__(256) k_fabgram(
    const float* __restrict__ x, const float* __restrict__ Wa, const float* __restrict__ ba,
    const float* __restrict__ Wb, const float* __restrict__ bb)
{
    extern __shared__ float sm[];
    float* xs  = sm;                 // [c=64][4t*32v] = 8192
    float* Wab = sm + 8192;          // [s*32+r][stride65] = 6240
    float* fs  = sm + 8192 + 6240;   // [(s*2+side)][64k][32v] = 12288
    int n = blockIdx.x, seg = blockIdx.y, tid = threadIdx.x;
    int tseg0 = seg * 64;

    for (int idx = tid; idx < 3 * 32 * 64; idx += 256) {
        int s = idx / 2048, r = (idx / 64) % 32, c = idx % 64;
        float w = (r < 16) ? Wa[s * 1024 + r * 64 + c] : Wb[s * 1024 + (r - 16) * 64 + c];
        Wab[(s * 32 + r) * 65 + c] = w;
    }
    int ig = tid & 7;
    int vq = (tid >> 3) & 7;
    int tloc = tid >> 6;

    float bias[3][4];
#pragma unroll
    for (int s = 0; s < 3; s++)
#pragma unroll
        for (int j = 0; j < 4; j++) {
            int r = ig * 4 + j;
            bias[s][j] = (r < 16) ? ba[s * 16 + r] : bb[s * 16 + (r - 16)];
        }
    int side = ig >> 2;
    int gv = tid >> 3, gw4 = (tid & 7) * 4;

    float gacc[3][4];
#pragma unroll
    for (int s = 0; s < 3; s++)
#pragma unroll
        for (int q = 0; q < 4; q++) gacc[s][q] = 0.f;

    for (int sub = 0; sub < 16; sub++) {
        int t0 = tseg0 + sub * 4;
        for (int idx = tid; idx < 8192; idx += 256) {
            int c = idx >> 7, r = idx & 127, t = r >> 5, v = r & 31;
            xs[idx] = (v < 25) ? x[(((size_t)n * 64 + c) * 512 + t0 + t) * 25 + v] : 0.f;
        }
        __syncthreads();
        float4 facc[3][4];
#pragma unroll
        for (int s = 0; s < 3; s++)
#pragma unroll
            for (int j = 0; j < 4; j++) {
                float b0 = bias[s][j];
                facc[s][j] = make_float4(b0, b0, b0, b0);
            }
        for (int c = 0; c < 64; c++) {
            float4 X = *(const float4*)&xs[c * 128 + tloc * 32 + vq * 4];
#pragma unroll
            for (int s = 0; s < 3; s++)
#pragma unroll
                for (int j = 0; j < 4; j++) {
                    float w = Wab[(s * 32 + ig * 4 + j) * 65 + c];
                    facc[s][j].x += w * X.x; facc[s][j].y += w * X.y;
                    facc[s][j].z += w * X.z; facc[s][j].w += w * X.w;
                }
        }
#pragma unroll
        for (int s = 0; s < 3; s++)
#pragma unroll
            for (int j = 0; j < 4; j++) {
                int kl = tloc * 16 + (ig & 3) * 4 + j;
                *(float4*)&fs[(s * 2 + side) * 2048 + kl * 32 + vq * 4] = facc[s][j];
            }
        __syncthreads();
#pragma unroll
        for (int s = 0; s < 3; s++) {
            const float* fap = &fs[(s * 2 + 0) * 2048];
            const float* fbp = &fs[(s * 2 + 1) * 2048];
            for (int kk = 0; kk < 64; kk++) {
                float fav = fap[kk * 32 + gv];
                float4 f4 = *(const float4*)&fbp[kk * 32 + gw4];
                gacc[s][0] += fav * f4.x; gacc[s][1] += fav * f4.y;
                gacc[s][2] += fav * f4.z; gacc[s][3] += fav * f4.w;
            }
        }
        __syncthreads();
    }
#pragma unroll
    for (int s = 0; s < 3; s++) {
        float* p = &g_Apart[((size_t)((n * 3 + s) * 8 + seg)) * 1024 + gv * 32 + gw4];
        p[0] = gacc[s][0]; p[1] = gacc[s][1]; p[2] = gacc[s][2]; p[3] = gacc[s][3];
    }
}

__global__ void k_gram2(const float* __restrict__ PA, const float* __restrict__ alpha) {
    int ns = blockIdx.x; int s = ns % 3;
    float al = alpha[0];
    for (int p = threadIdx.x; p < 625; p += 256) {
        int v = p / 25, w = p % 25;
        float sum = 0;
        for (int seg = 0; seg < 8; seg++)
            sum += g_Apart[((size_t)ns * 8 + seg) * 1024 + v * 32 + w];
        float A1 = tanhf(sum * (1.0f / 8192.0f));
        g_Aeff[ns * 625 + p] = PA[s * 625 + p] + al * A1;
    }
}

// ---------------- GCN stage1: z[slot][k] = x·Ae, bf16 split DIRECT to gmem ----------------
// grid (64 tchunk of 8t, 64 n), 256 thr, 3 CTAs/SM. Thread = (c-oct, w).
// Direct uint4 stores: 8 consecutive threads cover k 0..63 = 128B contiguous.
#define GCN1_SMEM 62800
__global__ void __launch_bounds__(256, 3) k_gcn1(const float* __restrict__ x) {
    extern __shared__ char s1raw[];
    float* xT = (float*)s1raw;                       // [tv=200][68c] 54400B
    float* ae = (float*)(s1raw + 54400);             // [3][25][28]   8400B
    int tcb = blockIdx.x, n = blockIdx.y;
    int t0 = tcb * 8, tid = threadIdx.x;

    for (int idx = tid; idx < 12800; idx += 256) {
        int c = idx / 200, tv = idx % 200;
        xT[tv * 68 + c] = x[(((size_t)n * 64 + c) * 512 + t0 + tv / 25) * 25 + tv % 25];
    }
    for (int idx = tid; idx < 2100; idx += 256) {
        int s = idx / 700, r = idx % 700, v = r / 28, w = r % 28;
        ae[idx] = (w < 25) ? g_Aeff[(size_t)(n * 3 + s) * 625 + v * 25 + w] : 0.f;
    }
    __syncthreads();

    int co = (tid & 7) * 8, w = tid >> 3;   // w 0..31, active if <25
    unsigned* zh32 = (unsigned*)g_zh;
    unsigned* zl32 = (unsigned*)g_zl;

    if (w < 25) {
        for (int t = 0; t < 8; t++) {
            float acc[3][8];
#pragma unroll
            for (int s = 0; s < 3; s++)
#pragma unroll
                for (int i = 0; i < 8; i++) acc[s][i] = 0.f;
            for (int v = 0; v < 25; v++) {
                float4 X0 = *(const float4*)&xT[(t * 25 + v) * 68 + co];
                float4 X1 = *(const float4*)&xT[(t * 25 + v) * 68 + co + 4];
#pragma unroll
                for (int s = 0; s < 3; s++) {
                    float e = ae[s * 700 + v * 28 + w];
                    acc[s][0] += X0.x * e; acc[s][1] += X0.y * e;
                    acc[s][2] += X0.z * e; acc[s][3] += X0.w * e;
                    acc[s][4] += X1.x * e; acc[s][5] += X1.y * e;
                    acc[s][6] += X1.z * e; acc[s][7] += X1.w * e;
                }
            }
            size_t slotw = ((size_t)n * 12800 + (size_t)(t0 + t) * 25 + w) * 96;
#pragma unroll
            for (int s = 0; s < 3; s++) {
                unsigned uh0, ul0, uh1, ul1, uh2, ul2, uh3, ul3;
                split2(acc[s][0], acc[s][1], uh0, ul0);
                split2(acc[s][2], acc[s][3], uh1, ul1);
                split2(acc[s][4], acc[s][5], uh2, ul2);
                split2(acc[s][6], acc[s][7], uh3, ul3);
                size_t woff = slotw + s * 32 + (co >> 1);
                *(uint4*)&zh32[woff] = make_uint4(uh0, uh1, uh2, uh3);
                *(uint4*)&zl32[woff] = make_uint4(ul0, ul1, ul2, ul3);
            }
        }
    }
}

// ---------------- GCN stage2: y[o][slot] = Wd2[k][o]^T · z[slot][k], MMA + BN1 ----------------
// grid (100 slot-chunks of 128, 64 n), 512 thr.
#define GCN2_SMEM 192512
__global__ void __launch_bounds__(512) k_gcn2() {
    extern __shared__ char s2raw[];
    __nv_bfloat16* Azh = (__nv_bfloat16*)s2raw;              // [128][200] 51200B
    __nv_bfloat16* Wh = (__nv_bfloat16*)(s2raw + 102400);    // [192][72]  27648B
    float* zout = (float*)(s2raw + 157696);                  // [64][136]  34816B
    int blk = blockIdx.x, n = blockIdx.y;
    int slot0 = blk * 128, tid = threadIdx.x;
    int wid = tid >> 5, lane = tid & 31;

    // stage A (z tile) hi/lo
    {
        unsigned* dh = (unsigned*)s2raw;
        unsigned* dl = (unsigned*)(s2raw + 51200);
        const unsigned* shp = (const unsigned*)g_zh;
        const unsigned* slp = (const unsigned*)g_zl;
        for (int idx = tid; idx < 12288; idx += 512) {
            int row = idx / 96, kp = idx % 96;
            size_t src = ((size_t)n * 12800 + slot0 + row) * 96 + kp;
            dh[row * 100 + kp] = shp[src];
            dl[row * 100 + kp] = slp[src];
        }
    }
    // stage W hi/lo
    {
        unsigned* dh = (unsigned*)(s2raw + 102400);
        unsigned* dl = (unsigned*)(s2raw + 130048);
        const unsigned* shp = (const unsigned*)g_Wd2h;
        const unsigned* slp = (const unsigned*)g_Wd2l;
        for (int idx = tid; idx < 6912; idx += 512) { dh[idx] = shp[idx]; dl[idx] = slp[idx]; }
    }
    __syncthreads();

    int ng = wid & 3, m0 = wid >> 2;  // tiles m0, m0+4; n-group fixed
    float acc[2][8];
#pragma unroll
    for (int q = 0; q < 2; q++)
#pragma unroll
        for (int i = 0; i < 8; i++) acc[q][i] = 0.f;

    unsigned baseA = su32(Azh), baseW = su32(Wh);
    int arow = lane & 15, acol8 = (lane >> 4) << 3;
#pragma unroll
    for (int ks = 0; ks < 12; ks++) {
        int k0 = ks * 16;
        unsigned bh[4], bl[4];
        unsigned baddr = baseW + (unsigned)(((k0 + arow) * 72 + ng * 16 + acol8) * 2);
        ldsm4t(baddr, bh);
        ldsm4t(baddr + 27648u, bl);
#pragma unroll
        for (int q = 0; q < 2; q++) {
            int mt = m0 + q * 4;
            unsigned aaddr = baseA + (unsigned)(((mt * 16 + arow) * 200 + k0 + acol8) * 2);
            unsigned ah[4], al[4];
            ldsm4(aaddr, ah);
            ldsm4(aaddr + 51200u, al);
            mma16816(&acc[q][0], ah, &bh[0]);
            mma16816(&acc[q][0], ah, &bl[0]);
            mma16816(&acc[q][0], al, &bh[0]);
            mma16816(&acc[q][4], ah, &bh[2]);
            mma16816(&acc[q][4], ah, &bl[2]);
            mma16816(&acc[q][4], al, &bh[2]);
        }
    }
    __syncthreads();   // A region reuse below; MMA reads done
#pragma unroll
    for (int q = 0; q < 2; q++) {
        int r0 = (m0 + q * 4) * 16 + (lane >> 2);
#pragma unroll
        for (int h = 0; h < 2; h++) {
            int o0 = ng * 16 + h * 8 + ((lane & 3) << 1);
            zout[o0 * 136 + r0] = acc[q][h * 4 + 0];
            zout[(o0 + 1) * 136 + r0] = acc[q][h * 4 + 1];
            zout[o0 * 136 + r0 + 8] = acc[q][h * 4 + 2];
            zout[(o0 + 1) * 136 + r0 + 8] = acc[q][h * 4 + 3];
        }
    }
    __syncthreads();
    for (int idx = tid; idx < 8192; idx += 512) {
        int o = idx / 128, sl = idx % 128;
        g_y[(size_t)(n * 64 + o) * 12800 + slot0 + sl] = zout[o * 136 + sl];
    }
    // BN1 partials
    float* red = (float*)s2raw;
    {
        int o = tid >> 3, sub = tid & 7;
        float a = 0, b = 0;
        for (int sl = sub; sl < 128; sl += 8) {
            float v = zout[o * 136 + sl];
            a += v; b += v * v;
        }
        red[tid] = a; red[512 + tid] = b;
    }
    __syncthreads();
    if (tid < 64) {
        float a = 0, b = 0;
        for (int p = 0; p < 8; p++) { a += red[tid * 8 + p]; b += red[512 + tid * 8 + p]; }
        g_bnS[(size_t)tid * 8192 + n * 100 + blk] = a;
        g_bnQ[(size_t)tid * 8192 + n * 100 + blk] = b;
    }
}

__global__ void k_bnfin(int cnt, int off) {
    __shared__ float s1[256], s2[256];
    int c = blockIdx.x, tid = threadIdx.x;
    float a = 0, b = 0;
    for (int i = tid; i < cnt; i += 256) {
        a += g_bnS[(size_t)c * 8192 + i];
        b += g_bnQ[(size_t)c * 8192 + i];
    }
    s1[tid] = a; s2[tid] = b; __syncthreads();
    for (int st = 128; st > 0; st >>= 1) {
        if (tid < st) { s1[tid] += s1[tid + st]; s2[tid] += s2[tid + st]; }
        __syncthreads();
    }
    if (tid == 0) {
        float m = s1[0] / 819200.0f;
        float v = s2[0] / 819200.0f - m * m;
        g_stats[off + c] = m;
        g_stats[off + 64 + c] = rsqrtf(v + 1e-5f);
    }
}

// BN1 apply + residual + relu -> g_y2, fused T-mean partials -> g_meanT
__global__ void __launch_bounds__(256) k_bnapply_mt(
    const float* __restrict__ gm, const float* __restrict__ bt, const float* __restrict__ x)
{
    __shared__ float red[8 * 33];
    int nc = blockIdx.x, tid = threadIdx.x, lane = tid & 31, tg = tid >> 5;
    int c = nc & 63;
    float m = g_stats[c], r = g_stats[64 + c];
    float sc = r * gm[c], sb = bt[c] - m * sc;
    float a = 0;
    if (lane < 25) {
        size_t base = (size_t)nc * 12800 + lane;
        for (int t = tg; t < 512; t += 8) {
            float y = g_y[base + t * 25];
            float o = fmaxf(y * sc + sb + x[base + t * 25], 0.f);
            g_y2[base + t * 25] = o;
            a += o;
        }
        red[tg * 33 + lane] = a;
    }
    __syncthreads();
    if (tid < 25) {
        float s = 0;
        for (int g = 0; g < 8; g++) s += red[g * 33 + tid];
        g_meanT[nc * 25 + tid] = s * (1.f / 512.f);
    }
}

// ---------------- attention chain ----------------
__global__ void k_sattn(const float* __restrict__ saw, const float* __restrict__ sab) {
    int n = blockIdx.x, v = threadIdx.x;
    if (v < 25) {
        float acc = sab[0];
        for (int c = 0; c < 64; c++) {
            const float* m = &g_meanT[(n * 64 + c) * 25];
            const float* w = &saw[c * 25];
#pragma unroll
            for (int j = 0; j < 25; j++) {
                int vv = v + j - 12;
                if (vv >= 0 && vv < 25) acc += w[j] * m[vv];
            }
        }
        g_gs[n * 25 + v] = 1.f + 1.f / (1.f + expf(-acc));
    }
}

__global__ void __launch_bounds__(256) k_meanV() {
    __shared__ float sgs[25];
    int nc = blockIdx.x, tid = threadIdx.x;
    int n = nc >> 6;
    if (tid < 25) sgs[tid] = g_gs[n * 25 + tid];
    __syncthreads();
    for (int t = tid; t < 512; t += 256) {
        const float* row = &g_y2[(size_t)nc * 12800 + t * 25];
        float a = 0;
#pragma unroll
        for (int v = 0; v < 25; v++) a += row[v] * sgs[v];
        g_meanV[nc * 512 + t] = a * (1.f / 25.f);
    }
}

__global__ void k_tattn(const float* __restrict__ taw, const float* __restrict__ tab) {
    int n = blockIdx.x, tid = threadIdx.x;
    for (int t = tid; t < 512; t += 256) {
        float acc = tab[0];
        for (int c = 0; c < 64; c++) {
            const float* m = &g_meanV[(n * 64 + c) * 512];
            const float* w = &taw[c * 9];
#pragma unroll
            for (int j = 0; j < 9; j++) {
                int tt = t + j - 4;
                if (tt >= 0 && tt < 512) acc += w[j] * m[tt];
            }
        }
        g_gt[n * 512 + t] = 1.f + 1.f / (1.f + expf(-acc));
    }
}

__global__ void k_cse(const float* __restrict__ f1w, const float* __restrict__ f1b,
                      const float* __restrict__ f2w, const float* __restrict__ f2b) {
    __shared__ float sm3[64], sh[32];
    int n = blockIdx.x, c = threadIdx.x;
    const float* m = &g_meanV[(n * 64 + c) * 512];
    const float* gt = &g_gt[n * 512];
    float a = 0;
    for (int t = 0; t < 512; t++) a += m[t] * gt[t];
    sm3[c] = a * (1.f / 512.f);
    __syncthreads();
    if (c < 32) {
        float h = f1b[c];
        for (int k = 0; k < 64; k++) h += f1w[c * 64 + k] * sm3[k];
        sh[c] = fmaxf(h, 0.f);
    }
    __syncthreads();
    float o = f2b[c];
    for (int j = 0; j < 32; j++) o += f2w[c * 32 + j] * sh[j];
    g_gc[n * 64 + c] = 1.f + 1.f / (1.f + expf(-o));
}

// ---------------- TCN via mma.sync bf16-split + BN2 partial epilogue ----------------
#define TCN_SMEM 189440
__global__ void __launch_bounds__(512) k_tcn() {
    extern __shared__ char smemraw[];
    __nv_bfloat16* Ah = (__nv_bfloat16*)smemraw;                 // [408][72]
    __nv_bfloat16* Wh = (__nv_bfloat16*)(smemraw + 117504);      // [64][72]
    __nv_bfloat16* Wl = (__nv_bfloat16*)(smemraw + 126720);
    float* zout = (float*)(smemraw + 135936);                    // [64][209]
    __shared__ float gsg[25], gtg[17], gcg[64];
    int tcb = blockIdx.x, n = blockIdx.y;
    int t0 = tcb * 8, tid = threadIdx.x;
    int wid = tid >> 5, lane = tid & 31;

    if (tid < 25) gsg[tid] = g_gs[n * 25 + tid];
    if (tid >= 32 && tid < 49) {
        int tin = t0 - 4 + (tid - 32);
        gtg[tid - 32] = (tin >= 0 && tin < 512) ? g_gt[n * 512 + tin] : 0.f;
    }
    if (tid >= 64 && tid < 128) gcg[tid - 64] = g_gc[n * 64 + (tid - 64)];
    __syncthreads();

    // vectorized staging: thread handles a c-pair at one s
    for (int idx = tid; idx < 408 * 32; idx += 512) {
        int cp = idx / 408, s = idx - cp * 408;
        int tvg = (t0 - 4) * 25 + s;
        float v0 = 0.f, v1 = 0.f;
        if (tvg >= 0 && tvg < 12800) {
            float g = gsg[s % 25] * gtg[s / 25];
            v0 = g_y2[(size_t)(n * 64 + 2 * cp) * 12800 + tvg] * g * gcg[2 * cp];
            v1 = g_y2[(size_t)(n * 64 + 2 * cp + 1) * 12800 + tvg] * g * gcg[2 * cp + 1];
        }
        unsigned uh, ul;
        split2(v0, v1, uh, ul);
        *(unsigned*)&Ah[s * 72 + 2 * cp] = uh;
        *(unsigned*)&Ah[29376 + s * 72 + 2 * cp] = ul;
    }

    // warp -> fixed n-group, strided m-tiles
    int ng = wid & 3, w4 = wid >> 2;
    int nbase = ng * 16;
    int mt[4], cnt = 0;
    for (int m = w4; m < 13; m += 4) mt[cnt++] = m;
    float acc[4][8];
#pragma unroll
    for (int q = 0; q < 4; q++)
#pragma unroll
        for (int i = 0; i < 8; i++) acc[q][i] = 0.f;

    unsigned baseA = su32(Ah), baseW = su32(Wh);
    int arow = lane & 15, acol8 = (lane >> 4) << 3;

    for (int tap = 0; tap < 9; tap++) {
        __syncthreads();
        for (int idx = tid; idx < 4608; idx += 512) {
            Wh[idx] = g_Wt9h[tap * 4608 + idx];
            Wl[idx] = g_Wt9l[tap * 4608 + idx];
        }
        __syncthreads();
#pragma unroll
        for (int ks = 0; ks < 4; ks++) {
            int c0 = ks * 16;
            unsigned bh[4], bl[4];
            unsigned baddr = baseW + (unsigned)(((c0 + arow) * 72 + nbase + acol8) * 2);
            ldsm4t(baddr, bh);
            ldsm4t(baddr + 9216u, bl);
#pragma unroll
            for (int q = 0; q < 4; q++) {
                if (q >= cnt) break;
                int rb = mt[q] * 16 + 25 * tap;
                unsigned aaddr = baseA + (unsigned)(((rb + arow) * 72 + c0 + acol8) * 2);
                unsigned ah[4], al[4];
                ldsm4(aaddr, ah);
                ldsm4(aaddr + 58752u, al);
                mma16816(&acc[q][0], ah, &bh[0]);
                mma16816(&acc[q][0], ah, &bl[0]);
                mma16816(&acc[q][0], al, &bh[0]);
                mma16816(&acc[q][4], ah, &bh[2]);
                mma16816(&acc[q][4], ah, &bl[2]);
                mma16816(&acc[q][4], al, &bh[2]);
            }
        }
    }
    __syncthreads();
#pragma unroll
    for (int q = 0; q < 4; q++) {
        if (q >= cnt) break;
#pragma unroll
        for (int h = 0; h < 2; h++) {
            int o0 = nbase + h * 8 + ((lane & 3) << 1);
            int r0 = mt[q] * 16 + (lane >> 2);
            zout[o0 * 209 + r0] = acc[q][h * 4 + 0];
            zout[(o0 + 1) * 209 + r0] = acc[q][h * 4 + 1];
            zout[o0 * 209 + r0 + 8] = acc[q][h * 4 + 2];
            zout[(o0 + 1) * 209 + r0 + 8] = acc[q][h * 4 + 3];
        }
    }
    __syncthreads();
    for (int idx = tid; idx < 64 * 200; idx += 512) {
        int o = idx / 200, sl = idx - o * 200;
        g_y[((size_t)(n * 64 + o) * 512 + t0) * 25 + sl] = zout[o * 209 + sl];
    }
    float* red = (float*)Wh;
    {
        int o = tid >> 3, sub = tid & 7;
        float a = 0, b = 0;
        for (int sl = sub; sl < 200; sl += 8) {
            float v = zout[o * 209 + sl];
            a += v; b += v * v;
        }
        red[tid] = a; red[512 + tid] = b;
    }
    __syncthreads();
    if (tid < 64) {
        float a = 0, b = 0;
        for (int p = 0; p < 8; p++) { a += red[tid * 8 + p]; b += red[512 + tid * 8 + p]; }
        g_bnS[(size_t)tid * 8192 + n * 64 + tcb] = a;
        g_bnQ[(size_t)tid * 8192 + n * 64 + tcb] = b;
    }
}

// final: out = relu(bn2(g_y) + x), vectorized
__global__ void __launch_bounds__(256) k_bnapply2(
    const float* __restrict__ gm, const float* __restrict__ bt,
    const float* __restrict__ x, float* __restrict__ out)
{
    size_t i4 = (size_t)blockIdx.x * 256 + threadIdx.x;
    size_t flat = i4 * 4;
    int c = (int)((flat / 12800) % 64);
    float m = g_stats[128 + c], r = g_stats[192 + c];
    float sc = r * gm[c];
    float sb = bt[c] - m * sc;
    float4 Y = *(const float4*)&g_y[flat];
    float4 X = *(const float4*)&x[flat];
    float4 O;
    O.x = fmaxf(Y.x * sc + sb + X.x, 0.f);
    O.y = fmaxf(Y.y * sc + sb + X.y, 0.f);
    O.z = fmaxf(Y.z * sc + sb + X.z, 0.f);
    O.w = fmaxf(Y.w * sc + sb + X.w, 0.f);
    *(float4*)&out[flat] = O;
}

// ---------------- launcher ----------------
extern "C" void kernel_launch(void* const* d_in, const int* in_sizes, int n_in,
                              void* d_out, int out_size) {
    const float* x   = (const float*)d_in[0];
    const float* PA  = (const float*)d_in[1];
    const float* alp = (const float*)d_in[2];
    const float* Wa  = (const float*)d_in[3];
    const float* ba  = (const float*)d_in[4];
    const float* Wb  = (const float*)d_in[5];
    const float* bb  = (const float*)d_in[6];
    const float* Wd  = (const float*)d_in[7];
    const float* bng = (const float*)d_in[9];
    const float* bnb = (const float*)d_in[10];
    const float* saw = (const float*)d_in[11];
    const float* sab = (const float*)d_in[12];
    const float* taw = (const float*)d_in[13];
    const float* tab = (const float*)d_in[14];
    const float* f1w = (const float*)d_in[15];
    const float* f1b = (const float*)d_in[16];
    const float* f2w = (const float*)d_in[17];
    const float* f2b = (const float*)d_in[18];
    const float* tw  = (const float*)d_in[19];
    const float* tbg = (const float*)d_in[21];
    const float* tbb = (const float*)d_in[22];
    float* out = (float*)d_out;

    cudaFuncSetAttribute(k_fabgram, cudaFuncAttributeMaxDynamicSharedMemorySize, 106880);
    cudaFuncSetAttribute(k_gcn1, cudaFuncAttributeMaxDynamicSharedMemorySize, GCN1_SMEM);
    cudaFuncSetAttribute(k_gcn2, cudaFuncAttributeMaxDynamicSharedMemorySize, GCN2_SMEM);
    cudaFuncSetAttribute(k_tcn, cudaFuncAttributeMaxDynamicSharedMemorySize, TCN_SMEM);

    k_prep<<<64, 256>>>(Wd, tw);
    k_fabgram<<<dim3(64, 8), 256, 106880>>>(x, Wa, ba, Wb, bb);
    k_gram2<<<192, 256>>>(PA, alp);
    k_gcn1<<<dim3(64, 64), 256, GCN1_SMEM>>>(x);
    k_gcn2<<<dim3(100, 64), 512, GCN2_SMEM>>>();
    k_bnfin<<<64, 256>>>(6400, 0);
    k_bnapply_mt<<<4096, 256>>>(bng, bnb, x);
    k_sattn<<<64, 32>>>(saw, sab);
    k_meanV<<<4096, 256>>>();
    k_tattn<<<64, 256>>>(taw, tab);
    k_cse<<<64, 64>>>(f1w, f1b, f2w, f2b);
    k_tcn<<<dim3(64, 64), 512, TCN_SMEM>>>();
    k_bnfin<<<64, 256>>>(4096, 128);
    k_bnapply2<<<51200, 256>>>(tbg, tbb, x, out);
}